// round 6
// baseline (speedup 1.0000x reference)
#include <cuda_runtime.h>
#include <cuda_bf16.h>
#include <cstdint>

#define H_ 16
#define D_ 1024
#define DK 64
#define B_ 2
#define S_ 2048
#define M_ (B_ * S_)   // 4096

typedef __nv_bfloat16 bf16;

// ---------------- device scratch ----------------
__device__ bf16 g_Xh [M_ * D_],     g_Xl [M_ * D_];
__device__ bf16 g_Wqh[3 * D_ * D_], g_Wql[3 * D_ * D_];
__device__ bf16 g_Woh[D_ * D_],     g_Wol[D_ * D_];
__device__ bf16 g_Aih[M_ * D_],     g_Ail[M_ * D_];
__device__ bf16 g_Qh[B_*H_*S_*DK],  g_Ql[B_*H_*S_*DK];   // pre-scaled 1/8
__device__ bf16 g_Kh[B_*H_*S_*DK],  g_Kl[B_*H_*S_*DK];
__device__ bf16 g_Vh[B_*H_*DK*S_],  g_Vl[B_*H_*DK*S_];   // V^T [b,h,d,s]
__device__ float g_atn[M_ * D_];                          // ch = d*H+h

// ---------------- helpers ----------------
__device__ __forceinline__ void bsplit(float x, bf16& h, bf16& l) {
    h = __float2bfloat16(x);
    l = __float2bfloat16(x - __bfloat162float(h));
}
__device__ __forceinline__ uint32_t pk(bf16 a, bf16 b) {
    return (uint32_t)__bfloat16_as_ushort(a) |
           ((uint32_t)__bfloat16_as_ushort(b) << 16);
}
__device__ __forceinline__ uint32_t smem_u32(const void* p) {
    return (uint32_t)__cvta_generic_to_shared(p);
}
__device__ __forceinline__ void ldsm4(uint32_t r[4], uint32_t addr) {
    asm volatile("ldmatrix.sync.aligned.m8n8.x4.shared.b16 {%0,%1,%2,%3}, [%4];"
                 : "=r"(r[0]), "=r"(r[1]), "=r"(r[2]), "=r"(r[3]) : "r"(addr));
}
__device__ __forceinline__ void mma_bf16(float c[4], const uint32_t a[4],
                                         uint32_t b0, uint32_t b1) {
    asm volatile(
        "mma.sync.aligned.m16n8k16.row.col.f32.bf16.bf16.f32 "
        "{%0,%1,%2,%3}, {%4,%5,%6,%7}, {%8,%9}, {%0,%1,%2,%3};\n"
        : "+f"(c[0]), "+f"(c[1]), "+f"(c[2]), "+f"(c[3])
        : "r"(a[0]), "r"(a[1]), "r"(a[2]), "r"(a[3]), "r"(b0), "r"(b1));
}
__device__ __forceinline__ void cpa16(uint32_t saddr, const void* g) {
    asm volatile("cp.async.cg.shared.global [%0], [%1], 16;"
                 :: "r"(saddr), "l"(g));
}
__device__ __forceinline__ void cp_commit() {
    asm volatile("cp.async.commit_group;");
}
template <int N>
__device__ __forceinline__ void cp_wait() {
    asm volatile("cp.async.wait_group %0;" :: "n"(N));
}

// ---------------- pre-split pass ----------------
__global__ __launch_bounds__(256) void split_kernel(
    const float* __restrict__ x, bf16* __restrict__ h, bf16* __restrict__ l, int n)
{
    const int i = (blockIdx.x * 256 + threadIdx.x) * 4;
    if (i >= n) return;
    float4 v = *(const float4*)(x + i);
    bf16 h0, h1, h2, h3, l0, l1, l2, l3;
    bsplit(v.x, h0, l0); bsplit(v.y, h1, l1);
    bsplit(v.z, h2, l2); bsplit(v.w, h3, l3);
    *(uint32_t*)(h + i)     = pk(h0, h1);
    *(uint32_t*)(h + i + 2) = pk(h2, h3);
    *(uint32_t*)(l + i)     = pk(l0, l1);
    *(uint32_t*)(l + i + 2) = pk(l2, l3);
}

// ---------------------------------------------------------------------------
// bf16 split-3 GEMM, 4-stage cp.async pipeline, TERM-MAJOR mma ordering.
// Block 128x128, BK=16, 256 thr, 8 warps (4Mx2N), warp tile 32x64.
// smem/stage: 4 arrays x 128 x GS bf16.  4 stages = 98304 B (dynamic).
// ---------------------------------------------------------------------------
#define GS 24
#define GAR (128 * GS)
#define GARB (GAR * 2)           // 6144 B per array
#define GSGB (4 * GARB)          // 24576 B per stage
#define GST 4                    // stages
template <int MODE>
__global__ __launch_bounds__(256, 2) void gemm_bf16(
    const bf16* __restrict__ Ah, const bf16* __restrict__ Al,
    const bf16* __restrict__ Bh, const bf16* __restrict__ Bl,
    float* __restrict__ C, int M, int N, int K)
{
    extern __shared__ __align__(16) bf16 sm[];

    const int t = threadIdx.x, lane = t & 31, wid = t >> 5;
    const int g = lane >> 2, l4 = lane & 3;
    const int warpM = wid >> 1, warpN = wid & 1;
    const int m0 = blockIdx.y * 128, n0 = blockIdx.x * 128;

    float c[2][8][4];
#pragma unroll
    for (int i = 0; i < 2; i++)
#pragma unroll
        for (int j = 0; j < 8; j++)
#pragma unroll
            for (int v = 0; v < 4; v++) c[i][j][v] = 0.0f;

    const int srow = t >> 1, sseg = (t & 1) * 8;
    const bf16* pAh = Ah + (size_t)(m0 + srow) * K + sseg;
    const bf16* pAl = Al + (size_t)(m0 + srow) * K + sseg;
    const bf16* pBh = Bh + (size_t)(n0 + srow) * K + sseg;
    const bf16* pBl = Bl + (size_t)(n0 + srow) * K + sseg;
    const uint32_t stBase = smem_u32(&sm[srow * GS + sseg]);

    const int fr = lane & 15, fc = (lane >> 4) * 8;
    uint32_t aA[2];
#pragma unroll
    for (int ma = 0; ma < 2; ma++)
        aA[ma] = smem_u32(&sm[(warpM * 32 + ma * 16 + fr) * GS + fc]);
    uint32_t aB[4];
#pragma unroll
    for (int hq = 0; hq < 4; hq++)
        aB[hq] = smem_u32(&sm[(warpN * 64 + hq * 16 + fr) * GS + fc]) + 2 * GARB;

    const int KT = K / 16;

    // preload stages 0..2
#pragma unroll
    for (int s = 0; s < 3; s++) {
        const int k0 = s * 16;
        const uint32_t sb = stBase + s * GSGB;
        cpa16(sb + 0 * GARB, pAh + k0);
        cpa16(sb + 1 * GARB, pAl + k0);
        cpa16(sb + 2 * GARB, pBh + k0);
        cpa16(sb + 3 * GARB, pBl + k0);
        cp_commit();
    }

    for (int kt = 0; kt < KT; kt++) {
        const int st = kt & (GST - 1);
        if (kt == KT - 1) cp_wait<0>(); else cp_wait<2>();
        __syncthreads();

        if (kt + 3 < KT) {
            const int s2 = (kt + 3) & (GST - 1);
            const int k0 = (kt + 3) * 16;
            const uint32_t sb = stBase + s2 * GSGB;
            cpa16(sb + 0 * GARB, pAh + k0);
            cpa16(sb + 1 * GARB, pAl + k0);
            cpa16(sb + 2 * GARB, pBh + k0);
            cpa16(sb + 3 * GARB, pBl + k0);
        }
        cp_commit();

        const uint32_t sb = st * GSGB;
        uint32_t fAh[2][4], fAl[2][4];
        ldsm4(fAh[0], aA[0] + sb); ldsm4(fAh[1], aA[1] + sb);
        ldsm4(fAl[0], aA[0] + sb + GARB); ldsm4(fAl[1], aA[1] + sb + GARB);

#pragma unroll
        for (int half = 0; half < 2; half++) {
            uint32_t t0[4], t1[4], u0[4], u1[4];
            ldsm4(t0, aB[half * 2 + 0] + sb);
            ldsm4(t1, aB[half * 2 + 1] + sb);
            ldsm4(u0, aB[half * 2 + 0] + sb + GARB);
            ldsm4(u1, aB[half * 2 + 1] + sb + GARB);
            const uint32_t bh[4][2] = {{t0[0], t0[2]}, {t0[1], t0[3]},
                                       {t1[0], t1[2]}, {t1[1], t1[3]}};
            const uint32_t bl[4][2] = {{u0[0], u0[2]}, {u0[1], u0[3]},
                                       {u1[0], u1[2]}, {u1[1], u1[3]}};
            // term-major: hi*hi, hi*lo, lo*hi — 8 independent MMAs per term
#pragma unroll
            for (int na = 0; na < 4; na++)
#pragma unroll
                for (int ma = 0; ma < 2; ma++)
                    mma_bf16(c[ma][half * 4 + na], fAh[ma], bh[na][0], bh[na][1]);
#pragma unroll
            for (int na = 0; na < 4; na++)
#pragma unroll
                for (int ma = 0; ma < 2; ma++)
                    mma_bf16(c[ma][half * 4 + na], fAh[ma], bl[na][0], bl[na][1]);
#pragma unroll
            for (int na = 0; na < 4; na++)
#pragma unroll
                for (int ma = 0; ma < 2; ma++)
                    mma_bf16(c[ma][half * 4 + na], fAl[ma], bh[na][0], bh[na][1]);
        }
    }

    // epilogue
#pragma unroll
    for (int ma = 0; ma < 2; ma++)
#pragma unroll
        for (int na = 0; na < 8; na++)
#pragma unroll
            for (int v = 0; v < 4; v++) {
                const int m = m0 + warpM * 32 + ma * 16 + g + ((v >= 2) ? 8 : 0);
                const int n = n0 + warpN * 64 + na * 8 + 2 * l4 + (v & 1);
                const float val = c[ma][na][v];
                if (MODE == 0) {
                    C[(size_t)m * N + n] = val;
                } else {
                    const int s = m & (S_ - 1), b = m >> 11;
                    const int sel = n >> 10, e = n & 1023;
                    const int hh = e & 15, d = e >> 4;
                    bf16 hi, lo;
                    if (sel == 2) {
                        bsplit(val, hi, lo);
                        const size_t vi = (((size_t)(b * H_ + hh)) * DK + d) * S_ + s;
                        g_Vh[vi] = hi; g_Vl[vi] = lo;
                    } else {
                        const size_t idx = (((size_t)(b * H_ + hh)) * S_ + s) * DK + d;
                        if (sel == 0) {
                            bsplit(val * 0.125f, hi, lo);
                            g_Qh[idx] = hi; g_Ql[idx] = lo;
                        } else {
                            bsplit(val, hi, lo);
                            g_Kh[idx] = hi; g_Kl[idx] = lo;
                        }
                    }
                }
            }
}

// ---------------------------------------------------------------------------
// Flash attention, bf16 split-3, q128/kv64, 2-stage cp.async, TERM-MAJOR mma.
// ---------------------------------------------------------------------------
#define AS 72
#define QAR (128 * AS)
#define KVAR (64 * AS)
#define KVARB (KVAR * 2)
#define KVSGB (4 * KVARB)
__global__ __launch_bounds__(256, 2) void attn_bf16()
{
    extern __shared__ __align__(16) bf16 sm[];
    bf16* sQh = sm;
    bf16* sQl = sm + QAR;
    bf16* sKV = sm + 2 * QAR;

    const int t = threadIdx.x, lane = t & 31, wid = t >> 5;
    const int g = lane >> 2, l4 = lane & 3;
    const int qt = blockIdx.x, hh = blockIdx.y, b = blockIdx.z;
    const int bhid = b * H_ + hh;
    const int q0 = qt * 128;
    const int wq = wid * 16;

    {
        const int row = t >> 1, cs = (t & 1) * 32;
        const bf16* gqh = g_Qh + ((size_t)bhid * S_ + q0 + row) * DK + cs;
        const bf16* gql = g_Ql + ((size_t)bhid * S_ + q0 + row) * DK + cs;
        const uint32_t dqh = smem_u32(&sQh[row * AS + cs]);
        const uint32_t dql = smem_u32(&sQl[row * AS + cs]);
#pragma unroll
        for (int u = 0; u < 4; u++) {
            cpa16(dqh + 16 * u, gqh + 8 * u);
            cpa16(dql + 16 * u, gql + 8 * u);
        }
    }

    const int kr = t >> 2, kcs = (t & 3) * 16;
    const bf16* gkh = g_Kh + ((size_t)bhid * S_ + kr) * DK + kcs;
    const bf16* gkl = g_Kl + ((size_t)bhid * S_ + kr) * DK + kcs;
    const bf16* gvh = g_Vh + ((size_t)bhid * DK + kr) * S_ + kcs;
    const bf16* gvl = g_Vl + ((size_t)bhid * DK + kr) * S_ + kcs;
    const uint32_t kvBase = smem_u32(&sKV[kr * AS + kcs]);

#pragma unroll
    for (int u = 0; u < 2; u++) {
        cpa16(kvBase + 0 * KVARB + 16 * u, gkh + 8 * u);
        cpa16(kvBase + 1 * KVARB + 16 * u, gkl + 8 * u);
        cpa16(kvBase + 2 * KVARB + 16 * u, gvh + 8 * u);
        cpa16(kvBase + 3 * KVARB + 16 * u, gvl + 8 * u);
    }
    cp_commit();

    const int fr = lane & 15, fc = (lane >> 4) * 8;
    const uint32_t aQh = smem_u32(&sQh[(wq + fr) * AS + fc]);
    const uint32_t aQl = smem_u32(&sQl[(wq + fr) * AS + fc]);
    uint32_t aK[4], aV[4];
#pragma unroll
    for (int hq = 0; hq < 4; hq++) {
        const uint32_t rowb = smem_u32(&sKV[(hq * 16 + fr) * AS + fc]);
        aK[hq] = rowb;
        aV[hq] = rowb + 2 * KVARB;
    }

    float o[8][4];
#pragma unroll
    for (int na = 0; na < 8; na++)
#pragma unroll
        for (int v = 0; v < 4; v++) o[na][v] = 0.0f;
    float m0r = -1e30f, m1r = -1e30f, l0r = 0.0f, l1r = 0.0f;

    const int NT = S_ / 64;
    for (int jt = 0; jt < NT; jt++) {
        cp_wait<0>();
        __syncthreads();

        if (jt + 1 < NT) {
            const uint32_t sb = kvBase + ((jt + 1) & 1) * KVSGB;
            const int kro = (jt + 1) * 64 * DK;
            const int vco = (jt + 1) * 64;
#pragma unroll
            for (int u = 0; u < 2; u++) {
                cpa16(sb + 0 * KVARB + 16 * u, gkh + kro + 8 * u);
                cpa16(sb + 1 * KVARB + 16 * u, gkl + kro + 8 * u);
                cpa16(sb + 2 * KVARB + 16 * u, gvh + vco + 8 * u);
                cpa16(sb + 3 * KVARB + 16 * u, gvl + vco + 8 * u);
            }
        }
        cp_commit();

        const uint32_t sb = (jt & 1) * KVSGB;

        // ---- S = Q @ K^T (split-3, term-major) ----
        float sc[8][4];
#pragma unroll
        for (int na = 0; na < 8; na++)
#pragma unroll
            for (int v = 0; v < 4; v++) sc[na][v] = 0.0f;

#pragma unroll
        for (int kk = 0; kk < 4; kk++) {
            uint32_t qh[4], ql[4];
            ldsm4(qh, aQh + kk * 32);
            ldsm4(ql, aQl + kk * 32);
#pragma unroll
            for (int half = 0; half < 2; half++) {
                uint32_t t0[4], t1[4], u0[4], u1[4];
                ldsm4(t0, aK[half * 2 + 0] + sb + kk * 32);
                ldsm4(t1, aK[half * 2 + 1] + sb + kk * 32);
                ldsm4(u0, aK[half * 2 + 0] + sb + KVARB + kk * 32);
                ldsm4(u1, aK[half * 2 + 1] + sb + KVARB + kk * 32);
                const uint32_t bh[4][2] = {{t0[0], t0[2]}, {t0[1], t0[3]},
                                           {t1[0], t1[2]}, {t1[1], t1[3]}};
                const uint32_t bl[4][2] = {{u0[0], u0[2]}, {u0[1], u0[3]},
                                           {u1[0], u1[2]}, {u1[1], u1[3]}};
#pragma unroll
                for (int na = 0; na < 4; na++)
                    mma_bf16(sc[half * 4 + na], qh, bh[na][0], bh[na][1]);
#pragma unroll
                for (int na = 0; na < 4; na++)
                    mma_bf16(sc[half * 4 + na], qh, bl[na][0], bl[na][1]);
#pragma unroll
                for (int na = 0; na < 4; na++)
                    mma_bf16(sc[half * 4 + na], ql, bh[na][0], bh[na][1]);
            }
        }

        // ---- warp-local online softmax ----
        float rm0 = -1e30f, rm1 = -1e30f;
#pragma unroll
        for (int na = 0; na < 8; na++) {
            rm0 = fmaxf(rm0, fmaxf(sc[na][0], sc[na][1]));
            rm1 = fmaxf(rm1, fmaxf(sc[na][2], sc[na][3]));
        }
#pragma unroll
        for (int off = 1; off < 4; off <<= 1) {
            rm0 = fmaxf(rm0, __shfl_xor_sync(0xffffffffu, rm0, off));
            rm1 = fmaxf(rm1, __shfl_xor_sync(0xffffffffu, rm1, off));
        }
        const float mn0 = fmaxf(m0r, rm0), mn1 = fmaxf(m1r, rm1);
        const float cor0 = __expf(m0r - mn0), cor1 = __expf(m1r - mn1);
        float rs0 = 0.0f, rs1 = 0.0f;
#pragma unroll
        for (int na = 0; na < 8; na++) {
            sc[na][0] = __expf(sc[na][0] - mn0);
            sc[na][1] = __expf(sc[na][1] - mn0);
            sc[na][2] = __expf(sc[na][2] - mn1);
            sc[na][3] = __expf(sc[na][3] - mn1);
            rs0 += sc[na][0] + sc[na][1];
            rs1 += sc[na][2] + sc[na][3];
        }
#pragma unroll
        for (int off = 1; off < 4; off <<= 1) {
            rs0 += __shfl_xor_sync(0xffffffffu, rs0, off);
            rs1 += __shfl_xor_sync(0xffffffffu, rs1, off);
        }
        l0r = l0r * cor0 + rs0;
        l1r = l1r * cor1 + rs1;
        m0r = mn0; m1r = mn1;
#pragma unroll
        for (int na = 0; na < 8; na++) {
            o[na][0] *= cor0; o[na][1] *= cor0;
            o[na][2] *= cor1; o[na][3] *= cor1;
        }

        // ---- O += P @ V (split-3, term-major, P from registers) ----
#pragma unroll
        for (int kk = 0; kk < 4; kk++) {
            uint32_t pah[4], pal[4];
            {
                bf16 h0, h1, l0, l1;
                bsplit(sc[2 * kk][0], h0, l0); bsplit(sc[2 * kk][1], h1, l1);
                pah[0] = pk(h0, h1); pal[0] = pk(l0, l1);
                bsplit(sc[2 * kk][2], h0, l0); bsplit(sc[2 * kk][3], h1, l1);
                pah[1] = pk(h0, h1); pal[1] = pk(l0, l1);
                bsplit(sc[2 * kk + 1][0], h0, l0); bsplit(sc[2 * kk + 1][1], h1, l1);
                pah[2] = pk(h0, h1); pal[2] = pk(l0, l1);
                bsplit(sc[2 * kk + 1][2], h0, l0); bsplit(sc[2 * kk + 1][3], h1, l1);
                pah[3] = pk(h0, h1); pal[3] = pk(l0, l1);
            }
#pragma unroll
            for (int half = 0; half < 2; half++) {
                uint32_t t0[4], t1[4], u0[4], u1[4];
                ldsm4(t0, aV[half * 2 + 0] + sb + kk * 32);
                ldsm4(t1, aV[half * 2 + 1] + sb + kk * 32);
                ldsm4(u0, aV[half * 2 + 0] + sb + KVARB + kk * 32);
                ldsm4(u1, aV[half * 2 + 1] + sb + KVARB + kk * 32);
                const uint32_t bh[4][2] = {{t0[0], t0[2]}, {t0[1], t0[3]},
                                           {t1[0], t1[2]}, {t1[1], t1[3]}};
                const uint32_t bl[4][2] = {{u0[0], u0[2]}, {u0[1], u0[3]},
                                           {u1[0], u1[2]}, {u1[1], u1[3]}};
#pragma unroll
                for (int na = 0; na < 4; na++)
                    mma_bf16(o[half * 4 + na], pah, bh[na][0], bh[na][1]);
#pragma unroll
                for (int na = 0; na < 4; na++)
                    mma_bf16(o[half * 4 + na], pah, bl[na][0], bl[na][1]);
#pragma unroll
                for (int na = 0; na < 4; na++)
                    mma_bf16(o[half * 4 + na], pal, bh[na][0], bh[na][1]);
            }
        }
    }

    {
        const float inv0 = 1.0f / l0r, inv1 = 1.0f / l1r;
        const int s0 = q0 + wq + g, s1 = s0 + 8;
        float* d0 = g_atn + ((size_t)(b * S_ + s0)) * D_;
        float* d1 = g_atn + ((size_t)(b * S_ + s1)) * D_;
#pragma unroll
        for (int na = 0; na < 8; na++) {
            const int dd = na * 8 + 2 * l4;
            d0[dd * H_ + hh]       = o[na][0] * inv0;
            d0[(dd + 1) * H_ + hh] = o[na][1] * inv0;
            d1[dd * H_ + hh]       = o[na][2] * inv1;
            d1[(dd + 1) * H_ + hh] = o[na][3] * inv1;
        }
    }
}

// ---------------------------------------------------------------------------
extern "C" void kernel_launch(void* const* d_in, const int* in_sizes, int n_in,
                              void* d_out, int out_size)
{
    const float* xs    = (const float*)d_in[0];
    const float* w_qkv = (const float*)d_in[2];
    const float* w_out = (const float*)d_in[3];
    float* out = (float*)d_out;

    bf16 *Xh, *Xl, *Wqh, *Wql, *Woh, *Wol, *Aih, *Ail;
    float* atn_ptr;
    cudaGetSymbolAddress((void**)&Xh,  g_Xh);
    cudaGetSymbolAddress((void**)&Xl,  g_Xl);
    cudaGetSymbolAddress((void**)&Wqh, g_Wqh);
    cudaGetSymbolAddress((void**)&Wql, g_Wql);
    cudaGetSymbolAddress((void**)&Woh, g_Woh);
    cudaGetSymbolAddress((void**)&Wol, g_Wol);
    cudaGetSymbolAddress((void**)&Aih, g_Aih);
    cudaGetSymbolAddress((void**)&Ail, g_Ail);
    cudaGetSymbolAddress((void**)&atn_ptr, g_atn);

    const int gemm_smem = GST * GSGB;          // 98304
    cudaFuncSetAttribute(gemm_bf16<0>,
                         cudaFuncAttributeMaxDynamicSharedMemorySize, gemm_smem);
    cudaFuncSetAttribute(gemm_bf16<1>,
                         cudaFuncAttributeMaxDynamicSharedMemorySize, gemm_smem);

    // 0) pre-split inputs
    split_kernel<<<(M_ * D_) / 1024, 256>>>(xs, Xh, Xl, M_ * D_);
    split_kernel<<<(3 * D_ * D_) / 1024, 256>>>(w_qkv, Wqh, Wql, 3 * D_ * D_);
    split_kernel<<<(D_ * D_) / 1024, 256>>>(w_out, Woh, Wol, D_ * D_);

    // 1) QKV projection
    {
        dim3 grid(3 * D_ / 128, M_ / 128);
        gemm_bf16<1><<<grid, 256, gemm_smem>>>(Xh, Xl, Wqh, Wql, nullptr,
                                               M_, 3 * D_, D_);
    }

    // 2) flash attention
    {
        const int smem = (2 * QAR) * 2 + 2 * KVSGB;  // 110592
        cudaFuncSetAttribute(attn_bf16,
                             cudaFuncAttributeMaxDynamicSharedMemorySize, smem);
        dim3 grid(S_ / 128, H_, B_);
        attn_bf16<<<grid, 256, smem>>>();
    }

    // 3) out-projection
    split_kernel<<<(M_ * D_) / 1024, 256>>>(atn_ptr, Aih, Ail, M_ * D_);
    {
        dim3 grid(D_ / 128, M_ / 128);
        gemm_bf16<0><<<grid, 256, gemm_smem>>>(Aih, Ail, Woh, Wol, out,
                                               M_, D_, D_);
    }
}

// round 7
// speedup vs baseline: 1.0093x; 1.0093x over previous
#include <cuda_runtime.h>
#include <cuda_bf16.h>
#include <cstdint>

#define H_ 16
#define D_ 1024
#define DK 64
#define B_ 2
#define S_ 2048
#define M_ (B_ * S_)   // 4096

typedef __nv_bfloat16 bf16;

// ---------------- device scratch ----------------
__device__ bf16 g_Xh [M_ * D_],     g_Xl [M_ * D_];
__device__ bf16 g_Wqh[3 * D_ * D_], g_Wql[3 * D_ * D_];
__device__ bf16 g_Woh[D_ * D_],     g_Wol[D_ * D_];      // PERMUTED: [e][h*64+d]
__device__ bf16 g_Aih[M_ * D_],     g_Ail[M_ * D_];      // head-major [m][h*64+d]
__device__ bf16 g_Qh[B_*H_*S_*DK],  g_Ql[B_*H_*S_*DK];   // pre-scaled 1/8
__device__ bf16 g_Kh[B_*H_*S_*DK],  g_Kl[B_*H_*S_*DK];
__device__ bf16 g_Vh[B_*H_*DK*S_],  g_Vl[B_*H_*DK*S_];   // V^T [b,h,d,s]

// ---------------- helpers ----------------
__device__ __forceinline__ void bsplit(float x, bf16& h, bf16& l) {
    h = __float2bfloat16(x);
    l = __float2bfloat16(x - __bfloat162float(h));
}
__device__ __forceinline__ uint32_t pk(bf16 a, bf16 b) {
    return (uint32_t)__bfloat16_as_ushort(a) |
           ((uint32_t)__bfloat16_as_ushort(b) << 16);
}
__device__ __forceinline__ uint32_t smem_u32(const void* p) {
    return (uint32_t)__cvta_generic_to_shared(p);
}
__device__ __forceinline__ void ldsm4(uint32_t r[4], uint32_t addr) {
    asm volatile("ldmatrix.sync.aligned.m8n8.x4.shared.b16 {%0,%1,%2,%3}, [%4];"
                 : "=r"(r[0]), "=r"(r[1]), "=r"(r[2]), "=r"(r[3]) : "r"(addr));
}
__device__ __forceinline__ void mma_bf16(float c[4], const uint32_t a[4],
                                         uint32_t b0, uint32_t b1) {
    asm volatile(
        "mma.sync.aligned.m16n8k16.row.col.f32.bf16.bf16.f32 "
        "{%0,%1,%2,%3}, {%4,%5,%6,%7}, {%8,%9}, {%0,%1,%2,%3};\n"
        : "+f"(c[0]), "+f"(c[1]), "+f"(c[2]), "+f"(c[3])
        : "r"(a[0]), "r"(a[1]), "r"(a[2]), "r"(a[3]), "r"(b0), "r"(b1));
}
__device__ __forceinline__ void cpa16(uint32_t saddr, const void* g) {
    asm volatile("cp.async.cg.shared.global [%0], [%1], 16;"
                 :: "r"(saddr), "l"(g));
}
__device__ __forceinline__ void cp_commit() {
    asm volatile("cp.async.commit_group;");
}
template <int N>
__device__ __forceinline__ void cp_wait() {
    asm volatile("cp.async.wait_group %0;" :: "n"(N));
}

// ---------------- pre-split pass (contiguous) ----------------
__global__ __launch_bounds__(256) void split_kernel(
    const float* __restrict__ x, bf16* __restrict__ h, bf16* __restrict__ l, int n)
{
    const int i = (blockIdx.x * 256 + threadIdx.x) * 4;
    if (i >= n) return;
    float4 v = *(const float4*)(x + i);
    bf16 h0, h1, h2, h3, l0, l1, l2, l3;
    bsplit(v.x, h0, l0); bsplit(v.y, h1, l1);
    bsplit(v.z, h2, l2); bsplit(v.w, h3, l3);
    *(uint32_t*)(h + i)     = pk(h0, h1);
    *(uint32_t*)(h + i + 2) = pk(h2, h3);
    *(uint32_t*)(l + i)     = pk(l0, l1);
    *(uint32_t*)(l + i + 2) = pk(l2, l3);
}

// ---------------- w_out split with head-major column permutation ----------------
// out[e][h*64+d] = w_out[e][d*16+h]
__global__ __launch_bounds__(256) void split_wout(
    const float* __restrict__ w, bf16* __restrict__ oh, bf16* __restrict__ ol)
{
    const int j4 = (blockIdx.x * 256 + threadIdx.x) * 4;  // output index
    const int e  = j4 >> 10;
    const int jj = j4 & 1023;
    const int h  = jj >> 6, d = jj & 63;
    const float* src = w + (size_t)e * D_ + h;
    float v0 = src[(d + 0) * 16];
    float v1 = src[(d + 1) * 16];
    float v2 = src[(d + 2) * 16];
    float v3 = src[(d + 3) * 16];
    bf16 h0, h1, h2, h3, l0, l1, l2, l3;
    bsplit(v0, h0, l0); bsplit(v1, h1, l1);
    bsplit(v2, h2, l2); bsplit(v3, h3, l3);
    *(uint32_t*)(oh + j4)     = pk(h0, h1);
    *(uint32_t*)(oh + j4 + 2) = pk(h2, h3);
    *(uint32_t*)(ol + j4)     = pk(l0, l1);
    *(uint32_t*)(ol + j4 + 2) = pk(l2, l3);
}

// ---------------------------------------------------------------------------
// bf16 split-3 GEMM, BK=32 (2 panels/stage), 2-stage cp.async double buffer.
// Block 128x128, 256 thr, 8 warps (4Mx2N), warp tile 32x64.
// smem: 2 stages x 4 arrays x 2 panels x (128 x GS bf16) = 98304 B.
// ---------------------------------------------------------------------------
#define GS 24
#define GPNLB (128 * GS * 2)      // panel bytes: 6144
#define GARRB (2 * GPNLB)         // per-array per-stage: 12288
#define GSGB (4 * GARRB)          // per-stage: 49152
template <int MODE>
__global__ __launch_bounds__(256, 2) void gemm_bf16(
    const bf16* __restrict__ Ah, const bf16* __restrict__ Al,
    const bf16* __restrict__ Bh, const bf16* __restrict__ Bl,
    float* __restrict__ C, int M, int N, int K)
{
    extern __shared__ __align__(16) bf16 sm[];

    const int t = threadIdx.x, lane = t & 31, wid = t >> 5;
    const int g = lane >> 2, l4 = lane & 3;
    const int warpM = wid >> 1, warpN = wid & 1;
    const int m0 = blockIdx.y * 128, n0 = blockIdx.x * 128;

    float c[2][8][4];
#pragma unroll
    for (int i = 0; i < 2; i++)
#pragma unroll
        for (int j = 0; j < 8; j++)
#pragma unroll
            for (int v = 0; v < 4; v++) c[i][j][v] = 0.0f;

    const int srow = t >> 1, sseg = (t & 1) * 8;
    const bf16* pAh = Ah + (size_t)(m0 + srow) * K + sseg;
    const bf16* pAl = Al + (size_t)(m0 + srow) * K + sseg;
    const bf16* pBh = Bh + (size_t)(n0 + srow) * K + sseg;
    const bf16* pBl = Bl + (size_t)(n0 + srow) * K + sseg;
    const uint32_t stBase = smem_u32(&sm[srow * GS + sseg]);

    const int fr = lane & 15, fc = (lane >> 4) * 8;
    uint32_t aA[2];
#pragma unroll
    for (int ma = 0; ma < 2; ma++)
        aA[ma] = smem_u32(&sm[(warpM * 32 + ma * 16 + fr) * GS + fc]);
    uint32_t aB[4];
#pragma unroll
    for (int hq = 0; hq < 4; hq++)
        aB[hq] = smem_u32(&sm[(warpN * 64 + hq * 16 + fr) * GS + fc]) + 2 * GARRB;

    auto load_stage = [&](int c2, int s) {
        const uint32_t sb = stBase + s * GSGB;
#pragma unroll
        for (int p = 0; p < 2; p++) {
            const int k0 = c2 * 32 + p * 16;
            cpa16(sb + 0 * GARRB + p * GPNLB, pAh + k0);
            cpa16(sb + 1 * GARRB + p * GPNLB, pAl + k0);
            cpa16(sb + 2 * GARRB + p * GPNLB, pBh + k0);
            cpa16(sb + 3 * GARRB + p * GPNLB, pBl + k0);
        }
    };

    const int KT2 = K / 32;
    load_stage(0, 0);
    cp_commit();

    for (int kt2 = 0; kt2 < KT2; kt2++) {
        const int st = kt2 & 1;
        cp_wait<0>();
        __syncthreads();

        if (kt2 + 1 < KT2) load_stage(kt2 + 1, st ^ 1);
        cp_commit();

        const uint32_t stOff = st * GSGB;
#pragma unroll
        for (int p = 0; p < 2; p++) {
            const uint32_t sb = stOff + p * GPNLB;
            uint32_t fAh[2][4], fAl[2][4];
            ldsm4(fAh[0], aA[0] + sb); ldsm4(fAh[1], aA[1] + sb);
            ldsm4(fAl[0], aA[0] + sb + GARRB); ldsm4(fAl[1], aA[1] + sb + GARRB);

#pragma unroll
            for (int half = 0; half < 2; half++) {
                uint32_t t0[4], t1[4], u0[4], u1[4];
                ldsm4(t0, aB[half * 2 + 0] + sb);
                ldsm4(t1, aB[half * 2 + 1] + sb);
                ldsm4(u0, aB[half * 2 + 0] + sb + GARRB);
                ldsm4(u1, aB[half * 2 + 1] + sb + GARRB);
                const uint32_t bh[4][2] = {{t0[0], t0[2]}, {t0[1], t0[3]},
                                           {t1[0], t1[2]}, {t1[1], t1[3]}};
                const uint32_t bl[4][2] = {{u0[0], u0[2]}, {u0[1], u0[3]},
                                           {u1[0], u1[2]}, {u1[1], u1[3]}};
#pragma unroll
                for (int na = 0; na < 4; na++)
#pragma unroll
                    for (int ma = 0; ma < 2; ma++) {
                        mma_bf16(c[ma][half * 4 + na], fAh[ma], bh[na][0], bh[na][1]);
                        mma_bf16(c[ma][half * 4 + na], fAh[ma], bl[na][0], bl[na][1]);
                        mma_bf16(c[ma][half * 4 + na], fAl[ma], bh[na][0], bh[na][1]);
                    }
            }
        }
    }

    // epilogue
#pragma unroll
    for (int ma = 0; ma < 2; ma++)
#pragma unroll
        for (int na = 0; na < 8; na++)
#pragma unroll
            for (int v = 0; v < 4; v++) {
                const int m = m0 + warpM * 32 + ma * 16 + g + ((v >= 2) ? 8 : 0);
                const int n = n0 + warpN * 64 + na * 8 + 2 * l4 + (v & 1);
                const float val = c[ma][na][v];
                if (MODE == 0) {
                    C[(size_t)m * N + n] = val;
                } else {
                    const int s = m & (S_ - 1), b = m >> 11;
                    const int sel = n >> 10, e = n & 1023;
                    const int hh = e & 15, d = e >> 4;
                    bf16 hi, lo;
                    if (sel == 2) {
                        bsplit(val, hi, lo);
                        const size_t vi = (((size_t)(b * H_ + hh)) * DK + d) * S_ + s;
                        g_Vh[vi] = hi; g_Vl[vi] = lo;
                    } else {
                        const size_t idx = (((size_t)(b * H_ + hh)) * S_ + s) * DK + d;
                        if (sel == 0) {
                            bsplit(val * 0.125f, hi, lo);
                            g_Qh[idx] = hi; g_Ql[idx] = lo;
                        } else {
                            bsplit(val, hi, lo);
                            g_Kh[idx] = hi; g_Kl[idx] = lo;
                        }
                    }
                }
            }
}

// ---------------------------------------------------------------------------
// Flash attention, bf16 split-3, q128/kv64, 2-stage cp.async.
// Epilogue writes bf16 hi/lo directly, head-major layout [m][h*64+d].
// ---------------------------------------------------------------------------
#define AS 72
#define QAR (128 * AS)
#define KVAR (64 * AS)
#define KVARB (KVAR * 2)
#define KVSGB (4 * KVARB)
__global__ __launch_bounds__(256, 2) void attn_bf16()
{
    extern __shared__ __align__(16) bf16 sm[];
    bf16* sQh = sm;
    bf16* sQl = sm + QAR;
    bf16* sKV = sm + 2 * QAR;

    const int t = threadIdx.x, lane = t & 31, wid = t >> 5;
    const int g = lane >> 2, l4 = lane & 3;
    const int qt = blockIdx.x, hh = blockIdx.y, b = blockIdx.z;
    const int bhid = b * H_ + hh;
    const int q0 = qt * 128;
    const int wq = wid * 16;

    {
        const int row = t >> 1, cs = (t & 1) * 32;
        const bf16* gqh = g_Qh + ((size_t)bhid * S_ + q0 + row) * DK + cs;
        const bf16* gql = g_Ql + ((size_t)bhid * S_ + q0 + row) * DK + cs;
        const uint32_t dqh = smem_u32(&sQh[row * AS + cs]);
        const uint32_t dql = smem_u32(&sQl[row * AS + cs]);
#pragma unroll
        for (int u = 0; u < 4; u++) {
            cpa16(dqh + 16 * u, gqh + 8 * u);
            cpa16(dql + 16 * u, gql + 8 * u);
        }
    }

    const int kr = t >> 2, kcs = (t & 3) * 16;
    const bf16* gkh = g_Kh + ((size_t)bhid * S_ + kr) * DK + kcs;
    const bf16* gkl = g_Kl + ((size_t)bhid * S_ + kr) * DK + kcs;
    const bf16* gvh = g_Vh + ((size_t)bhid * DK + kr) * S_ + kcs;
    const bf16* gvl = g_Vl + ((size_t)bhid * DK + kr) * S_ + kcs;
    const uint32_t kvBase = smem_u32(&sKV[kr * AS + kcs]);

#pragma unroll
    for (int u = 0; u < 2; u++) {
        cpa16(kvBase + 0 * KVARB + 16 * u, gkh + 8 * u);
        cpa16(kvBase + 1 * KVARB + 16 * u, gkl + 8 * u);
        cpa16(kvBase + 2 * KVARB + 16 * u, gvh + 8 * u);
        cpa16(kvBase + 3 * KVARB + 16 * u, gvl + 8 * u);
    }
    cp_commit();

    const int fr = lane & 15, fc = (lane >> 4) * 8;
    const uint32_t aQh = smem_u32(&sQh[(wq + fr) * AS + fc]);
    const uint32_t aQl = smem_u32(&sQl[(wq + fr) * AS + fc]);
    uint32_t aK[4], aV[4];
#pragma unroll
    for (int hq = 0; hq < 4; hq++) {
        const uint32_t rowb = smem_u32(&sKV[(hq * 16 + fr) * AS + fc]);
        aK[hq] = rowb;
        aV[hq] = rowb + 2 * KVARB;
    }

    float o[8][4];
#pragma unroll
    for (int na = 0; na < 8; na++)
#pragma unroll
        for (int v = 0; v < 4; v++) o[na][v] = 0.0f;
    float m0r = -1e30f, m1r = -1e30f, l0r = 0.0f, l1r = 0.0f;

    const int NT = S_ / 64;
    for (int jt = 0; jt < NT; jt++) {
        cp_wait<0>();
        __syncthreads();

        if (jt + 1 < NT) {
            const uint32_t sb = kvBase + ((jt + 1) & 1) * KVSGB;
            const int kro = (jt + 1) * 64 * DK;
            const int vco = (jt + 1) * 64;
#pragma unroll
            for (int u = 0; u < 2; u++) {
                cpa16(sb + 0 * KVARB + 16 * u, gkh + kro + 8 * u);
                cpa16(sb + 1 * KVARB + 16 * u, gkl + kro + 8 * u);
                cpa16(sb + 2 * KVARB + 16 * u, gvh + vco + 8 * u);
                cpa16(sb + 3 * KVARB + 16 * u, gvl + vco + 8 * u);
            }
        }
        cp_commit();

        const uint32_t sb = (jt & 1) * KVSGB;

        // ---- S = Q @ K^T (split-3) ----
        float sc[8][4];
#pragma unroll
        for (int na = 0; na < 8; na++)
#pragma unroll
            for (int v = 0; v < 4; v++) sc[na][v] = 0.0f;

#pragma unroll
        for (int kk = 0; kk < 4; kk++) {
            uint32_t qh[4], ql[4];
            ldsm4(qh, aQh + kk * 32);
            ldsm4(ql, aQl + kk * 32);
#pragma unroll
            for (int half = 0; half < 2; half++) {
                uint32_t t0[4], t1[4], u0[4], u1[4];
                ldsm4(t0, aK[half * 2 + 0] + sb + kk * 32);
                ldsm4(t1, aK[half * 2 + 1] + sb + kk * 32);
                ldsm4(u0, aK[half * 2 + 0] + sb + KVARB + kk * 32);
                ldsm4(u1, aK[half * 2 + 1] + sb + KVARB + kk * 32);
                const uint32_t bh[4][2] = {{t0[0], t0[2]}, {t0[1], t0[3]},
                                           {t1[0], t1[2]}, {t1[1], t1[3]}};
                const uint32_t bl[4][2] = {{u0[0], u0[2]}, {u0[1], u0[3]},
                                           {u1[0], u1[2]}, {u1[1], u1[3]}};
#pragma unroll
                for (int na = 0; na < 4; na++) {
                    mma_bf16(sc[half * 4 + na], qh, bh[na][0], bh[na][1]);
                    mma_bf16(sc[half * 4 + na], qh, bl[na][0], bl[na][1]);
                    mma_bf16(sc[half * 4 + na], ql, bh[na][0], bh[na][1]);
                }
            }
        }

        // ---- warp-local online softmax ----
        float rm0 = -1e30f, rm1 = -1e30f;
#pragma unroll
        for (int na = 0; na < 8; na++) {
            rm0 = fmaxf(rm0, fmaxf(sc[na][0], sc[na][1]));
            rm1 = fmaxf(rm1, fmaxf(sc[na][2], sc[na][3]));
        }
#pragma unroll
        for (int off = 1; off < 4; off <<= 1) {
            rm0 = fmaxf(rm0, __shfl_xor_sync(0xffffffffu, rm0, off));
            rm1 = fmaxf(rm1, __shfl_xor_sync(0xffffffffu, rm1, off));
        }
        const float mn0 = fmaxf(m0r, rm0), mn1 = fmaxf(m1r, rm1);
        const float cor0 = __expf(m0r - mn0), cor1 = __expf(m1r - mn1);
        float rs0 = 0.0f, rs1 = 0.0f;
#pragma unroll
        for (int na = 0; na < 8; na++) {
            sc[na][0] = __expf(sc[na][0] - mn0);
            sc[na][1] = __expf(sc[na][1] - mn0);
            sc[na][2] = __expf(sc[na][2] - mn1);
            sc[na][3] = __expf(sc[na][3] - mn1);
            rs0 += sc[na][0] + sc[na][1];
            rs1 += sc[na][2] + sc[na][3];
        }
#pragma unroll
        for (int off = 1; off < 4; off <<= 1) {
            rs0 += __shfl_xor_sync(0xffffffffu, rs0, off);
            rs1 += __shfl_xor_sync(0xffffffffu, rs1, off);
        }
        l0r = l0r * cor0 + rs0;
        l1r = l1r * cor1 + rs1;
        m0r = mn0; m1r = mn1;
#pragma unroll
        for (int na = 0; na < 8; na++) {
            o[na][0] *= cor0; o[na][1] *= cor0;
            o[na][2] *= cor1; o[na][3] *= cor1;
        }

        // ---- O += P @ V (split-3, P from registers) ----
#pragma unroll
        for (int kk = 0; kk < 4; kk++) {
            uint32_t pah[4], pal[4];
            {
                bf16 h0, h1, l0, l1;
                bsplit(sc[2 * kk][0], h0, l0); bsplit(sc[2 * kk][1], h1, l1);
                pah[0] = pk(h0, h1); pal[0] = pk(l0, l1);
                bsplit(sc[2 * kk][2], h0, l0); bsplit(sc[2 * kk][3], h1, l1);
                pah[1] = pk(h0, h1); pal[1] = pk(l0, l1);
                bsplit(sc[2 * kk + 1][0], h0, l0); bsplit(sc[2 * kk + 1][1], h1, l1);
                pah[2] = pk(h0, h1); pal[2] = pk(l0, l1);
                bsplit(sc[2 * kk + 1][2], h0, l0); bsplit(sc[2 * kk + 1][3], h1, l1);
                pah[3] = pk(h0, h1); pal[3] = pk(l0, l1);
            }
#pragma unroll
            for (int half = 0; half < 2; half++) {
                uint32_t t0[4], t1[4], u0[4], u1[4];
                ldsm4(t0, aV[half * 2 + 0] + sb + kk * 32);
                ldsm4(t1, aV[half * 2 + 1] + sb + kk * 32);
                ldsm4(u0, aV[half * 2 + 0] + sb + KVARB + kk * 32);
                ldsm4(u1, aV[half * 2 + 1] + sb + KVARB + kk * 32);
                const uint32_t bh[4][2] = {{t0[0], t0[2]}, {t0[1], t0[3]},
                                           {t1[0], t1[2]}, {t1[1], t1[3]}};
                const uint32_t bl[4][2] = {{u0[0], u0[2]}, {u0[1], u0[3]},
                                           {u1[0], u1[2]}, {u1[1], u1[3]}};
#pragma unroll
                for (int na = 0; na < 4; na++) {
                    mma_bf16(o[half * 4 + na], pah, bh[na][0], bh[na][1]);
                    mma_bf16(o[half * 4 + na], pah, bl[na][0], bl[na][1]);
                    mma_bf16(o[half * 4 + na], pal, bh[na][0], bh[na][1]);
                }
            }
        }
    }

    // epilogue: write bf16 hi/lo, head-major layout [m][hh*64 + d]
    {
        const float inv0 = 1.0f / l0r, inv1 = 1.0f / l1r;
        const int s0 = q0 + wq + g, s1 = s0 + 8;
        const int bm0 = b * S_ + s0, bm1 = b * S_ + s1;
#pragma unroll
        for (int na = 0; na < 8; na++) {
            const int dd = na * 8 + 2 * l4;
            const size_t i0 = (size_t)bm0 * D_ + hh * 64 + dd;
            const size_t i1 = (size_t)bm1 * D_ + hh * 64 + dd;
            bf16 h0, h1, l0, l1;
            bsplit(o[na][0] * inv0, h0, l0);
            bsplit(o[na][1] * inv0, h1, l1);
            *(uint32_t*)&g_Aih[i0] = pk(h0, h1);
            *(uint32_t*)&g_Ail[i0] = pk(l0, l1);
            bsplit(o[na][2] * inv1, h0, l0);
            bsplit(o[na][3] * inv1, h1, l1);
            *(uint32_t*)&g_Aih[i1] = pk(h0, h1);
            *(uint32_t*)&g_Ail[i1] = pk(l0, l1);
        }
    }
}

// ---------------------------------------------------------------------------
extern "C" void kernel_launch(void* const* d_in, const int* in_sizes, int n_in,
                              void* d_out, int out_size)
{
    const float* xs    = (const float*)d_in[0];
    const float* w_qkv = (const float*)d_in[2];
    const float* w_out = (const float*)d_in[3];
    float* out = (float*)d_out;

    bf16 *Xh, *Xl, *Wqh, *Wql, *Woh, *Wol, *Aih, *Ail;
    cudaGetSymbolAddress((void**)&Xh,  g_Xh);
    cudaGetSymbolAddress((void**)&Xl,  g_Xl);
    cudaGetSymbolAddress((void**)&Wqh, g_Wqh);
    cudaGetSymbolAddress((void**)&Wql, g_Wql);
    cudaGetSymbolAddress((void**)&Woh, g_Woh);
    cudaGetSymbolAddress((void**)&Wol, g_Wol);
    cudaGetSymbolAddress((void**)&Aih, g_Aih);
    cudaGetSymbolAddress((void**)&Ail, g_Ail);

    const int gemm_smem = 2 * GSGB;          // 98304
    cudaFuncSetAttribute(gemm_bf16<0>,
                         cudaFuncAttributeMaxDynamicSharedMemorySize, gemm_smem);
    cudaFuncSetAttribute(gemm_bf16<1>,
                         cudaFuncAttributeMaxDynamicSharedMemorySize, gemm_smem);

    // 0) pre-split inputs
    split_kernel<<<(M_ * D_) / 1024, 256>>>(xs, Xh, Xl, M_ * D_);
    split_kernel<<<(3 * D_ * D_) / 1024, 256>>>(w_qkv, Wqh, Wql, 3 * D_ * D_);
    split_wout<<<(D_ * D_) / 1024, 256>>>(w_out, Woh, Wol);

    // 1) QKV projection
    {
        dim3 grid(3 * D_ / 128, M_ / 128);
        gemm_bf16<1><<<grid, 256, gemm_smem>>>(Xh, Xl, Wqh, Wql, nullptr,
                                               M_, 3 * D_, D_);
    }

    // 2) flash attention (writes g_Aih/g_Ail directly)
    {
        const int smem = (2 * QAR) * 2 + 2 * KVSGB;  // 110592
        cudaFuncSetAttribute(attn_bf16,
                             cudaFuncAttributeMaxDynamicSharedMemorySize, smem);
        dim3 grid(S_ / 128, H_, B_);
        attn_bf16<<<grid, 256, smem>>>();
    }

    // 3) out-projection (permuted weights match head-major atn layout)
    {
        dim3 grid(D_ / 128, M_ / 128);
        gemm_bf16<0><<<grid, 256, gemm_smem>>>(Aih, Ail, Woh, Wol, out,
                                               M_, D_, D_);
    }
}

// round 8
// speedup vs baseline: 1.1301x; 1.1196x over previous
#include <cuda_runtime.h>
#include <cuda_bf16.h>
#include <cuda_fp16.h>
#include <cstdint>

#define H_ 16
#define D_ 1024
#define DK 64
#define B_ 2
#define S_ 2048
#define M_ (B_ * S_)   // 4096

typedef __nv_bfloat16 bf16;

// ---------------- device scratch ----------------
__device__ __half g_Xh [M_ * D_];                         // xs, fp16 (hi only)
__device__ __half g_Wqh[3 * D_ * D_], g_Wql[3 * D_ * D_]; // w_qkv fp16 hi/lo
__device__ __half g_Woh[D_ * D_],     g_Wol[D_ * D_];     // w_out PERMUTED [e][h*64+d]
__device__ __half g_Aih[M_ * D_];                         // atn head-major fp16
__device__ bf16 g_Qh[B_*H_*S_*DK],  g_Ql[B_*H_*S_*DK];    // pre-scaled 1/8
__device__ bf16 g_Kh[B_*H_*S_*DK],  g_Kl[B_*H_*S_*DK];
__device__ bf16 g_Vh[B_*H_*DK*S_],  g_Vl[B_*H_*DK*S_];    // V^T [b,h,d,s]

// ---------------- helpers ----------------
__device__ __forceinline__ void bsplit(float x, bf16& h, bf16& l) {
    h = __float2bfloat16(x);
    l = __float2bfloat16(x - __bfloat162float(h));
}
__device__ __forceinline__ uint32_t pk(bf16 a, bf16 b) {
    return (uint32_t)__bfloat16_as_ushort(a) |
           ((uint32_t)__bfloat16_as_ushort(b) << 16);
}
__device__ __forceinline__ uint32_t pkh(__half a, __half b) {
    return (uint32_t)__half_as_ushort(a) |
           ((uint32_t)__half_as_ushort(b) << 16);
}
__device__ __forceinline__ uint32_t smem_u32(const void* p) {
    return (uint32_t)__cvta_generic_to_shared(p);
}
__device__ __forceinline__ void ldsm4(uint32_t r[4], uint32_t addr) {
    asm volatile("ldmatrix.sync.aligned.m8n8.x4.shared.b16 {%0,%1,%2,%3}, [%4];"
                 : "=r"(r[0]), "=r"(r[1]), "=r"(r[2]), "=r"(r[3]) : "r"(addr));
}
__device__ __forceinline__ void mma_bf16(float c[4], const uint32_t a[4],
                                         uint32_t b0, uint32_t b1) {
    asm volatile(
        "mma.sync.aligned.m16n8k16.row.col.f32.bf16.bf16.f32 "
        "{%0,%1,%2,%3}, {%4,%5,%6,%7}, {%8,%9}, {%0,%1,%2,%3};\n"
        : "+f"(c[0]), "+f"(c[1]), "+f"(c[2]), "+f"(c[3])
        : "r"(a[0]), "r"(a[1]), "r"(a[2]), "r"(a[3]), "r"(b0), "r"(b1));
}
__device__ __forceinline__ void mma_f16(float c[4], const uint32_t a[4],
                                        uint32_t b0, uint32_t b1) {
    asm volatile(
        "mma.sync.aligned.m16n8k16.row.col.f32.f16.f16.f32 "
        "{%0,%1,%2,%3}, {%4,%5,%6,%7}, {%8,%9}, {%0,%1,%2,%3};\n"
        : "+f"(c[0]), "+f"(c[1]), "+f"(c[2]), "+f"(c[3])
        : "r"(a[0]), "r"(a[1]), "r"(a[2]), "r"(a[3]), "r"(b0), "r"(b1));
}
__device__ __forceinline__ void cpa16(uint32_t saddr, const void* g) {
    asm volatile("cp.async.cg.shared.global [%0], [%1], 16;"
                 :: "r"(saddr), "l"(g));
}
__device__ __forceinline__ void cp_commit() {
    asm volatile("cp.async.commit_group;");
}
template <int N>
__device__ __forceinline__ void cp_wait() {
    asm volatile("cp.async.wait_group %0;" :: "n"(N));
}

// ---------------- split passes ----------------
// fp16 hi only (for xs)
__global__ __launch_bounds__(256) void split_h(
    const float* __restrict__ x, __half* __restrict__ h, int n)
{
    const int i = (blockIdx.x * 256 + threadIdx.x) * 4;
    if (i >= n) return;
    float4 v = *(const float4*)(x + i);
    *(uint32_t*)(h + i)     = pkh(__float2half_rn(v.x), __float2half_rn(v.y));
    *(uint32_t*)(h + i + 2) = pkh(__float2half_rn(v.z), __float2half_rn(v.w));
}
// fp16 hi + lo (for w_qkv)
__global__ __launch_bounds__(256) void split_hl(
    const float* __restrict__ x, __half* __restrict__ h, __half* __restrict__ l, int n)
{
    const int i = (blockIdx.x * 256 + threadIdx.x) * 4;
    if (i >= n) return;
    float4 v = *(const float4*)(x + i);
    __half h0 = __float2half_rn(v.x), h1 = __float2half_rn(v.y);
    __half h2 = __float2half_rn(v.z), h3 = __float2half_rn(v.w);
    *(uint32_t*)(h + i)     = pkh(h0, h1);
    *(uint32_t*)(h + i + 2) = pkh(h2, h3);
    *(uint32_t*)(l + i)     = pkh(__float2half_rn(v.x - __half2float(h0)),
                                  __float2half_rn(v.y - __half2float(h1)));
    *(uint32_t*)(l + i + 2) = pkh(__float2half_rn(v.z - __half2float(h2)),
                                  __float2half_rn(v.w - __half2float(h3)));
}
// w_out fp16 hi/lo with head-major column permutation: out[e][h*64+d] = w[e][d*16+h]
__global__ __launch_bounds__(256) void split_wout_hl(
    const float* __restrict__ w, __half* __restrict__ oh, __half* __restrict__ ol)
{
    const int j4 = (blockIdx.x * 256 + threadIdx.x) * 4;
    const int e  = j4 >> 10;
    const int jj = j4 & 1023;
    const int h  = jj >> 6, d = jj & 63;
    const float* src = w + (size_t)e * D_ + h;
    float v0 = src[(d + 0) * 16];
    float v1 = src[(d + 1) * 16];
    float v2 = src[(d + 2) * 16];
    float v3 = src[(d + 3) * 16];
    __half h0 = __float2half_rn(v0), h1 = __float2half_rn(v1);
    __half h2 = __float2half_rn(v2), h3 = __float2half_rn(v3);
    *(uint32_t*)(oh + j4)     = pkh(h0, h1);
    *(uint32_t*)(oh + j4 + 2) = pkh(h2, h3);
    *(uint32_t*)(ol + j4)     = pkh(__float2half_rn(v0 - __half2float(h0)),
                                    __float2half_rn(v1 - __half2float(h1)));
    *(uint32_t*)(ol + j4 + 2) = pkh(__float2half_rn(v2 - __half2float(h2)),
                                    __float2half_rn(v3 - __half2float(h3)));
}

// ---------------------------------------------------------------------------
// fp16 2-term GEMM: C = A @ W^T,  C ≈ Ah·Wh + Ah·Wl  (A fp16, W fp16 hi/lo).
// Block 128x128, BK=32 (2 panels), 3-stage cp.async, 8 warps (4Mx2N).
// smem: 3 stages x 3 arrays x 2 panels x (128 x GS fp16) = 110592 B.
// ---------------------------------------------------------------------------
#define GS 24
#define GPNLB (128 * GS * 2)      // panel bytes: 6144
#define GARRB (2 * GPNLB)         // per-array per-stage: 12288
#define GSGB (3 * GARRB)          // per-stage: 36864
#define GST 3
template <int MODE>
__global__ __launch_bounds__(256, 2) void gemm_f16(
    const __half* __restrict__ Ah,
    const __half* __restrict__ Bh, const __half* __restrict__ Bl,
    float* __restrict__ C, int M, int N, int K)
{
    extern __shared__ __align__(16) __half sm[];

    const int t = threadIdx.x, lane = t & 31, wid = t >> 5;
    const int g = lane >> 2, l4 = lane & 3;
    const int warpM = wid >> 1, warpN = wid & 1;
    const int m0 = blockIdx.y * 128, n0 = blockIdx.x * 128;

    float c[2][8][4];
#pragma unroll
    for (int i = 0; i < 2; i++)
#pragma unroll
        for (int j = 0; j < 8; j++)
#pragma unroll
            for (int v = 0; v < 4; v++) c[i][j][v] = 0.0f;

    const int srow = t >> 1, sseg = (t & 1) * 8;
    const __half* pAh = Ah + (size_t)(m0 + srow) * K + sseg;
    const __half* pBh = Bh + (size_t)(n0 + srow) * K + sseg;
    const __half* pBl = Bl + (size_t)(n0 + srow) * K + sseg;
    const uint32_t stBase = smem_u32(&sm[srow * GS + sseg]);

    const int fr = lane & 15, fc = (lane >> 4) * 8;
    uint32_t aA[2];
#pragma unroll
    for (int ma = 0; ma < 2; ma++)
        aA[ma] = smem_u32(&sm[(warpM * 32 + ma * 16 + fr) * GS + fc]);
    uint32_t aB[4];
#pragma unroll
    for (int hq = 0; hq < 4; hq++)
        aB[hq] = smem_u32(&sm[(warpN * 64 + hq * 16 + fr) * GS + fc]) + GARRB;

    auto load_stage = [&](int c2, int s) {
        const uint32_t sb = stBase + s * GSGB;
#pragma unroll
        for (int p = 0; p < 2; p++) {
            const int k0 = c2 * 32 + p * 16;
            cpa16(sb + 0 * GARRB + p * GPNLB, pAh + k0);
            cpa16(sb + 1 * GARRB + p * GPNLB, pBh + k0);
            cpa16(sb + 2 * GARRB + p * GPNLB, pBl + k0);
        }
        cp_commit();
    };

    const int KT2 = K / 32;
    load_stage(0, 0);
    load_stage(1, 1);

    for (int kt2 = 0; kt2 < KT2; kt2++) {
        const int st = kt2 % GST;
        if (kt2 == KT2 - 1) cp_wait<0>(); else cp_wait<1>();
        __syncthreads();

        if (kt2 + 2 < KT2) {
            load_stage(kt2 + 2, (kt2 + 2) % GST);
        } else {
            cp_commit();
        }

        const uint32_t stOff = st * GSGB;
#pragma unroll
        for (int p = 0; p < 2; p++) {
            const uint32_t sb = stOff + p * GPNLB;
            uint32_t fA[2][4];
            ldsm4(fA[0], aA[0] + sb);
            ldsm4(fA[1], aA[1] + sb);
            uint32_t bh[4][4], bl[4][4];
#pragma unroll
            for (int hq = 0; hq < 4; hq++) {
                ldsm4(bh[hq], aB[hq] + sb);
                ldsm4(bl[hq], aB[hq] + sb + GARRB);
            }
            // hi term: 16 independent MMAs
#pragma unroll
            for (int na = 0; na < 8; na++) {
                const int hq = na >> 1, q = na & 1;
#pragma unroll
                for (int ma = 0; ma < 2; ma++)
                    mma_f16(c[ma][na], fA[ma], bh[hq][q], bh[hq][q + 2]);
            }
            // lo term: 16 independent MMAs
#pragma unroll
            for (int na = 0; na < 8; na++) {
                const int hq = na >> 1, q = na & 1;
#pragma unroll
                for (int ma = 0; ma < 2; ma++)
                    mma_f16(c[ma][na], fA[ma], bl[hq][q], bl[hq][q + 2]);
            }
        }
    }

    // epilogue (c[ma][na] covers n = n0 + warpN*64 + na*8 + 2*l4 + (v&1))
#pragma unroll
    for (int ma = 0; ma < 2; ma++)
#pragma unroll
        for (int na = 0; na < 8; na++)
#pragma unroll
            for (int v = 0; v < 4; v++) {
                const int m = m0 + warpM * 32 + ma * 16 + g + ((v >= 2) ? 8 : 0);
                const int n = n0 + warpN * 64 + na * 8 + 2 * l4 + (v & 1);
                const float val = c[ma][na][v];
                if (MODE == 0) {
                    C[(size_t)m * N + n] = val;
                } else {
                    const int s = m & (S_ - 1), b = m >> 11;
                    const int sel = n >> 10, e = n & 1023;
                    const int hh = e & 15, d = e >> 4;
                    bf16 hi, lo;
                    if (sel == 2) {
                        bsplit(val, hi, lo);
                        const size_t vi = (((size_t)(b * H_ + hh)) * DK + d) * S_ + s;
                        g_Vh[vi] = hi; g_Vl[vi] = lo;
                    } else {
                        const size_t idx = (((size_t)(b * H_ + hh)) * S_ + s) * DK + d;
                        if (sel == 0) {
                            bsplit(val * 0.125f, hi, lo);
                            g_Qh[idx] = hi; g_Ql[idx] = lo;
                        } else {
                            bsplit(val, hi, lo);
                            g_Kh[idx] = hi; g_Kl[idx] = lo;
                        }
                    }
                }
            }
}

// ---------------------------------------------------------------------------
// Flash attention, bf16 split-3, q128/kv64, 2-stage cp.async (unchanged math).
// Epilogue writes fp16 (hi only), head-major layout [m][h*64+d].
// ---------------------------------------------------------------------------
#define AS 72
#define QAR (128 * AS)
#define KVAR (64 * AS)
#define KVARB (KVAR * 2)
#define KVSGB (4 * KVARB)
__global__ __launch_bounds__(256, 2) void attn_bf16()
{
    extern __shared__ __align__(16) bf16 smb[];
    bf16* sQh = smb;
    bf16* sQl = smb + QAR;
    bf16* sKV = smb + 2 * QAR;

    const int t = threadIdx.x, lane = t & 31, wid = t >> 5;
    const int g = lane >> 2, l4 = lane & 3;
    const int qt = blockIdx.x, hh = blockIdx.y, b = blockIdx.z;
    const int bhid = b * H_ + hh;
    const int q0 = qt * 128;
    const int wq = wid * 16;

    {
        const int row = t >> 1, cs = (t & 1) * 32;
        const bf16* gqh = g_Qh + ((size_t)bhid * S_ + q0 + row) * DK + cs;
        const bf16* gql = g_Ql + ((size_t)bhid * S_ + q0 + row) * DK + cs;
        const uint32_t dqh = smem_u32(&sQh[row * AS + cs]);
        const uint32_t dql = smem_u32(&sQl[row * AS + cs]);
#pragma unroll
        for (int u = 0; u < 4; u++) {
            cpa16(dqh + 16 * u, gqh + 8 * u);
            cpa16(dql + 16 * u, gql + 8 * u);
        }
    }

    const int kr = t >> 2, kcs = (t & 3) * 16;
    const bf16* gkh = g_Kh + ((size_t)bhid * S_ + kr) * DK + kcs;
    const bf16* gkl = g_Kl + ((size_t)bhid * S_ + kr) * DK + kcs;
    const bf16* gvh = g_Vh + ((size_t)bhid * DK + kr) * S_ + kcs;
    const bf16* gvl = g_Vl + ((size_t)bhid * DK + kr) * S_ + kcs;
    const uint32_t kvBase = smem_u32(&sKV[kr * AS + kcs]);

#pragma unroll
    for (int u = 0; u < 2; u++) {
        cpa16(kvBase + 0 * KVARB + 16 * u, gkh + 8 * u);
        cpa16(kvBase + 1 * KVARB + 16 * u, gkl + 8 * u);
        cpa16(kvBase + 2 * KVARB + 16 * u, gvh + 8 * u);
        cpa16(kvBase + 3 * KVARB + 16 * u, gvl + 8 * u);
    }
    cp_commit();

    const int fr = lane & 15, fc = (lane >> 4) * 8;
    const uint32_t aQh = smem_u32(&sQh[(wq + fr) * AS + fc]);
    const uint32_t aQl = smem_u32(&sQl[(wq + fr) * AS + fc]);
    uint32_t aK[4], aV[4];
#pragma unroll
    for (int hq = 0; hq < 4; hq++) {
        const uint32_t rowb = smem_u32(&sKV[(hq * 16 + fr) * AS + fc]);
        aK[hq] = rowb;
        aV[hq] = rowb + 2 * KVARB;
    }

    float o[8][4];
#pragma unroll
    for (int na = 0; na < 8; na++)
#pragma unroll
        for (int v = 0; v < 4; v++) o[na][v] = 0.0f;
    float m0r = -1e30f, m1r = -1e30f, l0r = 0.0f, l1r = 0.0f;

    const int NT = S_ / 64;
    for (int jt = 0; jt < NT; jt++) {
        cp_wait<0>();
        __syncthreads();

        if (jt + 1 < NT) {
            const uint32_t sb = kvBase + ((jt + 1) & 1) * KVSGB;
            const int kro = (jt + 1) * 64 * DK;
            const int vco = (jt + 1) * 64;
#pragma unroll
            for (int u = 0; u < 2; u++) {
                cpa16(sb + 0 * KVARB + 16 * u, gkh + kro + 8 * u);
                cpa16(sb + 1 * KVARB + 16 * u, gkl + kro + 8 * u);
                cpa16(sb + 2 * KVARB + 16 * u, gvh + vco + 8 * u);
                cpa16(sb + 3 * KVARB + 16 * u, gvl + vco + 8 * u);
            }
        }
        cp_commit();

        const uint32_t sb = (jt & 1) * KVSGB;

        // ---- S = Q @ K^T (split-3) ----
        float sc[8][4];
#pragma unroll
        for (int na = 0; na < 8; na++)
#pragma unroll
            for (int v = 0; v < 4; v++) sc[na][v] = 0.0f;

#pragma unroll
        for (int kk = 0; kk < 4; kk++) {
            uint32_t qh[4], ql[4];
            ldsm4(qh, aQh + kk * 32);
            ldsm4(ql, aQl + kk * 32);
#pragma unroll
            for (int half = 0; half < 2; half++) {
                uint32_t t0[4], t1[4], u0[4], u1[4];
                ldsm4(t0, aK[half * 2 + 0] + sb + kk * 32);
                ldsm4(t1, aK[half * 2 + 1] + sb + kk * 32);
                ldsm4(u0, aK[half * 2 + 0] + sb + KVARB + kk * 32);
                ldsm4(u1, aK[half * 2 + 1] + sb + KVARB + kk * 32);
                const uint32_t bh[4][2] = {{t0[0], t0[2]}, {t0[1], t0[3]},
                                           {t1[0], t1[2]}, {t1[1], t1[3]}};
                const uint32_t bl[4][2] = {{u0[0], u0[2]}, {u0[1], u0[3]},
                                           {u1[0], u1[2]}, {u1[1], u1[3]}};
#pragma unroll
                for (int na = 0; na < 4; na++) {
                    mma_bf16(sc[half * 4 + na], qh, bh[na][0], bh[na][1]);
                    mma_bf16(sc[half * 4 + na], qh, bl[na][0], bl[na][1]);
                    mma_bf16(sc[half * 4 + na], ql, bh[na][0], bh[na][1]);
                }
            }
        }

        // ---- warp-local online softmax ----
        float rm0 = -1e30f, rm1 = -1e30f;
#pragma unroll
        for (int na = 0; na < 8; na++) {
            rm0 = fmaxf(rm0, fmaxf(sc[na][0], sc[na][1]));
            rm1 = fmaxf(rm1, fmaxf(sc[na][2], sc[na][3]));
        }
#pragma unroll
        for (int off = 1; off < 4; off <<= 1) {
            rm0 = fmaxf(rm0, __shfl_xor_sync(0xffffffffu, rm0, off));
            rm1 = fmaxf(rm1, __shfl_xor_sync(0xffffffffu, rm1, off));
        }
        const float mn0 = fmaxf(m0r, rm0), mn1 = fmaxf(m1r, rm1);
        const float cor0 = __expf(m0r - mn0), cor1 = __expf(m1r - mn1);
        float rs0 = 0.0f, rs1 = 0.0f;
#pragma unroll
        for (int na = 0; na < 8; na++) {
            sc[na][0] = __expf(sc[na][0] - mn0);
            sc[na][1] = __expf(sc[na][1] - mn0);
            sc[na][2] = __expf(sc[na][2] - mn1);
            sc[na][3] = __expf(sc[na][3] - mn1);
            rs0 += sc[na][0] + sc[na][1];
            rs1 += sc[na][2] + sc[na][3];
        }
#pragma unroll
        for (int off = 1; off < 4; off <<= 1) {
            rs0 += __shfl_xor_sync(0xffffffffu, rs0, off);
            rs1 += __shfl_xor_sync(0xffffffffu, rs1, off);
        }
        l0r = l0r * cor0 + rs0;
        l1r = l1r * cor1 + rs1;
        m0r = mn0; m1r = mn1;
#pragma unroll
        for (int na = 0; na < 8; na++) {
            o[na][0] *= cor0; o[na][1] *= cor0;
            o[na][2] *= cor1; o[na][3] *= cor1;
        }

        // ---- O += P @ V (split-3, P from registers) ----
#pragma unroll
        for (int kk = 0; kk < 4; kk++) {
            uint32_t pah[4], pal[4];
            {
                bf16 h0, h1, l0, l1;
                bsplit(sc[2 * kk][0], h0, l0); bsplit(sc[2 * kk][1], h1, l1);
                pah[0] = pk(h0, h1); pal[0] = pk(l0, l1);
                bsplit(sc[2 * kk][2], h0, l0); bsplit(sc[2 * kk][3], h1, l1);
                pah[1] = pk(h0, h1); pal[1] = pk(l0, l1);
                bsplit(sc[2 * kk + 1][0], h0, l0); bsplit(sc[2 * kk + 1][1], h1, l1);
                pah[2] = pk(h0, h1); pal[2] = pk(l0, l1);
                bsplit(sc[2 * kk + 1][2], h0, l0); bsplit(sc[2 * kk + 1][3], h1, l1);
                pah[3] = pk(h0, h1); pal[3] = pk(l0, l1);
            }
#pragma unroll
            for (int half = 0; half < 2; half++) {
                uint32_t t0[4], t1[4], u0[4], u1[4];
                ldsm4(t0, aV[half * 2 + 0] + sb + kk * 32);
                ldsm4(t1, aV[half * 2 + 1] + sb + kk * 32);
                ldsm4(u0, aV[half * 2 + 0] + sb + KVARB + kk * 32);
                ldsm4(u1, aV[half * 2 + 1] + sb + KVARB + kk * 32);
                const uint32_t bh[4][2] = {{t0[0], t0[2]}, {t0[1], t0[3]},
                                           {t1[0], t1[2]}, {t1[1], t1[3]}};
                const uint32_t bl[4][2] = {{u0[0], u0[2]}, {u0[1], u0[3]},
                                           {u1[0], u1[2]}, {u1[1], u1[3]}};
#pragma unroll
                for (int na = 0; na < 4; na++) {
                    mma_bf16(o[half * 4 + na], pah, bh[na][0], bh[na][1]);
                    mma_bf16(o[half * 4 + na], pah, bl[na][0], bl[na][1]);
                    mma_bf16(o[half * 4 + na], pal, bh[na][0], bh[na][1]);
                }
            }
        }
    }

    // epilogue: fp16 hi only, head-major [m][hh*64 + d]
    {
        const float inv0 = 1.0f / l0r, inv1 = 1.0f / l1r;
        const int s0 = q0 + wq + g, s1 = s0 + 8;
        const int bm0 = b * S_ + s0, bm1 = b * S_ + s1;
#pragma unroll
        for (int na = 0; na < 8; na++) {
            const int dd = na * 8 + 2 * l4;
            const size_t i0 = (size_t)bm0 * D_ + hh * 64 + dd;
            const size_t i1 = (size_t)bm1 * D_ + hh * 64 + dd;
            *(uint32_t*)&g_Aih[i0] = pkh(__float2half_rn(o[na][0] * inv0),
                                         __float2half_rn(o[na][1] * inv0));
            *(uint32_t*)&g_Aih[i1] = pkh(__float2half_rn(o[na][2] * inv1),
                                         __float2half_rn(o[na][3] * inv1));
        }
    }
}

// ---------------------------------------------------------------------------
extern "C" void kernel_launch(void* const* d_in, const int* in_sizes, int n_in,
                              void* d_out, int out_size)
{
    const float* xs    = (const float*)d_in[0];
    const float* w_qkv = (const float*)d_in[2];
    const float* w_out = (const float*)d_in[3];
    float* out = (float*)d_out;

    __half *Xh, *Wqh, *Wql, *Woh, *Wol, *Aih;
    cudaGetSymbolAddress((void**)&Xh,  g_Xh);
    cudaGetSymbolAddress((void**)&Wqh, g_Wqh);
    cudaGetSymbolAddress((void**)&Wql, g_Wql);
    cudaGetSymbolAddress((void**)&Woh, g_Woh);
    cudaGetSymbolAddress((void**)&Wol, g_Wol);
    cudaGetSymbolAddress((void**)&Aih, g_Aih);

    const int gemm_smem = GST * GSGB;          // 110592
    cudaFuncSetAttribute(gemm_f16<0>,
                         cudaFuncAttributeMaxDynamicSharedMemorySize, gemm_smem);
    cudaFuncSetAttribute(gemm_f16<1>,
                         cudaFuncAttributeMaxDynamicSharedMemorySize, gemm_smem);

    // 0) pre-split inputs
    split_h<<<(M_ * D_) / 1024, 256>>>(xs, Xh, M_ * D_);
    split_hl<<<(3 * D_ * D_) / 1024, 256>>>(w_qkv, Wqh, Wql, 3 * D_ * D_);
    split_wout_hl<<<(D_ * D_) / 1024, 256>>>(w_out, Woh, Wol);

    // 1) QKV projection (fp16 2-term)
    {
        dim3 grid(3 * D_ / 128, M_ / 128);
        gemm_f16<1><<<grid, 256, gemm_smem>>>(Xh, Wqh, Wql, nullptr,
                                              M_, 3 * D_, D_);
    }

    // 2) flash attention (bf16 split-3, writes g_Aih fp16 directly)
    {
        const int smem = (2 * QAR) * 2 + 2 * KVSGB;  // 110592
        cudaFuncSetAttribute(attn_bf16,
                             cudaFuncAttributeMaxDynamicSharedMemorySize, smem);
        dim3 grid(S_ / 128, H_, B_);
        attn_bf16<<<grid, 256, smem>>>();
    }

    // 3) out-projection (fp16 2-term, permuted weights)
    {
        dim3 grid(D_ / 128, M_ / 128);
        gemm_f16<0><<<grid, 256, gemm_smem>>>(Aih, Woh, Wol, out,
                                              M_, D_, D_);
    }
}

// round 9
// speedup vs baseline: 1.5023x; 1.3294x over previous
#include <cuda_runtime.h>
#include <cuda_fp16.h>
#include <cstdint>

#define H_ 16
#define D_ 1024
#define DK 64
#define B_ 2
#define S_ 2048
#define M_ (B_ * S_)   // 4096

// ---------------- device scratch ----------------
__device__ __half g_Xh [M_ * D_];                         // xs fp16
__device__ __half g_Wqh[3 * D_ * D_];                     // w_qkv fp16 (single)
__device__ __half g_Woh[D_ * D_],     g_Wol[D_ * D_];     // w_out PERMUTED [e][h*64+d], hi/lo
__device__ __half g_Aih[M_ * D_];                         // atn head-major fp16
__device__ __half g_Qh[B_*H_*S_*DK];                      // Q fp16, pre-scaled 1/8
__device__ __half g_Kh[B_*H_*S_*DK],  g_Kl[B_*H_*S_*DK];  // K fp16 hi/lo
__device__ __half g_Vh[B_*H_*DK*S_],  g_Vl[B_*H_*DK*S_];  // V^T [b,h,d,s] hi/lo

// ---------------- helpers ----------------
__device__ __forceinline__ void hsplit(float x, __half& h, __half& l) {
    h = __float2half_rn(x);
    l = __float2half_rn(x - __half2float(h));
}
__device__ __forceinline__ uint32_t pkh(__half a, __half b) {
    return (uint32_t)__half_as_ushort(a) |
           ((uint32_t)__half_as_ushort(b) << 16);
}
__device__ __forceinline__ uint32_t smem_u32(const void* p) {
    return (uint32_t)__cvta_generic_to_shared(p);
}
__device__ __forceinline__ void ldsm4(uint32_t r[4], uint32_t addr) {
    asm volatile("ldmatrix.sync.aligned.m8n8.x4.shared.b16 {%0,%1,%2,%3}, [%4];"
                 : "=r"(r[0]), "=r"(r[1]), "=r"(r[2]), "=r"(r[3]) : "r"(addr));
}
__device__ __forceinline__ void mma_f16(float c[4], const uint32_t a[4],
                                        uint32_t b0, uint32_t b1) {
    asm volatile(
        "mma.sync.aligned.m16n8k16.row.col.f32.f16.f16.f32 "
        "{%0,%1,%2,%3}, {%4,%5,%6,%7}, {%8,%9}, {%0,%1,%2,%3};\n"
        : "+f"(c[0]), "+f"(c[1]), "+f"(c[2]), "+f"(c[3])
        : "r"(a[0]), "r"(a[1]), "r"(a[2]), "r"(a[3]), "r"(b0), "r"(b1));
}
__device__ __forceinline__ void cpa16(uint32_t saddr, const void* g) {
    asm volatile("cp.async.cg.shared.global [%0], [%1], 16;"
                 :: "r"(saddr), "l"(g));
}
__device__ __forceinline__ void cp_commit() {
    asm volatile("cp.async.commit_group;");
}
template <int N>
__device__ __forceinline__ void cp_wait() {
    asm volatile("cp.async.wait_group %0;" :: "n"(N));
}

// ---------------- split passes ----------------
__global__ __launch_bounds__(256) void split_h(
    const float* __restrict__ x, __half* __restrict__ h, int n)
{
    const int i = (blockIdx.x * 256 + threadIdx.x) * 4;
    if (i >= n) return;
    float4 v = *(const float4*)(x + i);
    *(uint32_t*)(h + i)     = pkh(__float2half_rn(v.x), __float2half_rn(v.y));
    *(uint32_t*)(h + i + 2) = pkh(__float2half_rn(v.z), __float2half_rn(v.w));
}
// w_out fp16 hi/lo with head-major column permutation: out[e][h*64+d] = w[e][d*16+h]
__global__ __launch_bounds__(256) void split_wout_hl(
    const float* __restrict__ w, __half* __restrict__ oh, __half* __restrict__ ol)
{
    const int j4 = (blockIdx.x * 256 + threadIdx.x) * 4;
    const int e  = j4 >> 10;
    const int jj = j4 & 1023;
    const int h  = jj >> 6, d = jj & 63;
    const float* src = w + (size_t)e * D_ + h;
    float v0 = src[(d + 0) * 16];
    float v1 = src[(d + 1) * 16];
    float v2 = src[(d + 2) * 16];
    float v3 = src[(d + 3) * 16];
    __half h0, h1, h2, h3, l0, l1, l2, l3;
    hsplit(v0, h0, l0); hsplit(v1, h1, l1);
    hsplit(v2, h2, l2); hsplit(v3, h3, l3);
    *(uint32_t*)(oh + j4)     = pkh(h0, h1);
    *(uint32_t*)(oh + j4 + 2) = pkh(h2, h3);
    *(uint32_t*)(ol + j4)     = pkh(l0, l1);
    *(uint32_t*)(ol + j4 + 2) = pkh(l2, l3);
}

// ---------------------------------------------------------------------------
// fp16 GEMM: C = A @ W^T.  NLO=1: C = Ah·Wh.  NLO=2: C = Ah·Wh + Ah·Wl.
// Block 128x128, BK=32 (2 panels), 3-stage cp.async, 8 warps (4Mx2N).
// smem: 3 stages x (1+NLO) arrays x 2 panels x (128 x GS fp16).
// ---------------------------------------------------------------------------
#define GS 24
#define GPNLB (128 * GS * 2)      // panel bytes: 6144
#define GARRB (2 * GPNLB)         // per-array per-stage: 12288
#define GST 3
template <int MODE, int NLO>
__global__ __launch_bounds__(256, 2) void gemm_f16(
    const __half* __restrict__ Ah,
    const __half* __restrict__ Bh, const __half* __restrict__ Bl,
    float* __restrict__ C, int M, int N, int K)
{
    constexpr int SGB = (1 + NLO) * GARRB;   // stage bytes
    extern __shared__ __align__(16) __half sm[];

    const int t = threadIdx.x, lane = t & 31, wid = t >> 5;
    const int g = lane >> 2, l4 = lane & 3;
    const int warpM = wid >> 1, warpN = wid & 1;
    const int m0 = blockIdx.y * 128, n0 = blockIdx.x * 128;

    float c[2][8][4];
#pragma unroll
    for (int i = 0; i < 2; i++)
#pragma unroll
        for (int j = 0; j < 8; j++)
#pragma unroll
            for (int v = 0; v < 4; v++) c[i][j][v] = 0.0f;

    const int srow = t >> 1, sseg = (t & 1) * 8;
    const __half* pAh = Ah + (size_t)(m0 + srow) * K + sseg;
    const __half* pBh = Bh + (size_t)(n0 + srow) * K + sseg;
    const __half* pBl = (NLO == 2) ? (Bl + (size_t)(n0 + srow) * K + sseg) : nullptr;
    const uint32_t stBase = smem_u32(&sm[srow * GS + sseg]);

    const int fr = lane & 15, fc = (lane >> 4) * 8;
    uint32_t aA[2];
#pragma unroll
    for (int ma = 0; ma < 2; ma++)
        aA[ma] = smem_u32(&sm[(warpM * 32 + ma * 16 + fr) * GS + fc]);
    uint32_t aB[4];
#pragma unroll
    for (int hq = 0; hq < 4; hq++)
        aB[hq] = smem_u32(&sm[(warpN * 64 + hq * 16 + fr) * GS + fc]) + GARRB;

    auto load_stage = [&](int c2, int s) {
        const uint32_t sb = stBase + s * SGB;
#pragma unroll
        for (int p = 0; p < 2; p++) {
            const int k0 = c2 * 32 + p * 16;
            cpa16(sb + 0 * GARRB + p * GPNLB, pAh + k0);
            cpa16(sb + 1 * GARRB + p * GPNLB, pBh + k0);
            if (NLO == 2)
                cpa16(sb + 2 * GARRB + p * GPNLB, pBl + k0);
        }
        cp_commit();
    };

    const int KT2 = K / 32;
    load_stage(0, 0);
    load_stage(1, 1);

    for (int kt2 = 0; kt2 < KT2; kt2++) {
        const int st = kt2 % GST;
        if (kt2 == KT2 - 1) cp_wait<0>(); else cp_wait<1>();
        __syncthreads();

        if (kt2 + 2 < KT2) {
            load_stage(kt2 + 2, (kt2 + 2) % GST);
        } else {
            cp_commit();
        }

        const uint32_t stOff = st * SGB;
#pragma unroll
        for (int p = 0; p < 2; p++) {
            const uint32_t sb = stOff + p * GPNLB;
            uint32_t fA[2][4];
            ldsm4(fA[0], aA[0] + sb);
            ldsm4(fA[1], aA[1] + sb);
            uint32_t bh[4][4];
#pragma unroll
            for (int hq = 0; hq < 4; hq++)
                ldsm4(bh[hq], aB[hq] + sb);
#pragma unroll
            for (int na = 0; na < 8; na++) {
                const int hq = na >> 1, q = na & 1;
#pragma unroll
                for (int ma = 0; ma < 2; ma++)
                    mma_f16(c[ma][na], fA[ma], bh[hq][q], bh[hq][q + 2]);
            }
            if (NLO == 2) {
                uint32_t bl[4][4];
#pragma unroll
                for (int hq = 0; hq < 4; hq++)
                    ldsm4(bl[hq], aB[hq] + sb + GARRB);
#pragma unroll
                for (int na = 0; na < 8; na++) {
                    const int hq = na >> 1, q = na & 1;
#pragma unroll
                    for (int ma = 0; ma < 2; ma++)
                        mma_f16(c[ma][na], fA[ma], bl[hq][q], bl[hq][q + 2]);
                }
            }
        }
    }

    // epilogue
#pragma unroll
    for (int ma = 0; ma < 2; ma++)
#pragma unroll
        for (int na = 0; na < 8; na++)
#pragma unroll
            for (int v = 0; v < 4; v++) {
                const int m = m0 + warpM * 32 + ma * 16 + g + ((v >= 2) ? 8 : 0);
                const int n = n0 + warpN * 64 + na * 8 + 2 * l4 + (v & 1);
                const float val = c[ma][na][v];
                if (MODE == 0) {
                    C[(size_t)m * N + n] = val;
                } else {
                    const int s = m & (S_ - 1), b = m >> 11;
                    const int sel = n >> 10, e = n & 1023;
                    const int hh = e & 15, d = e >> 4;
                    __half hi, lo;
                    if (sel == 2) {
                        hsplit(val, hi, lo);
                        const size_t vi = (((size_t)(b * H_ + hh)) * DK + d) * S_ + s;
                        g_Vh[vi] = hi; g_Vl[vi] = lo;
                    } else {
                        const size_t idx = (((size_t)(b * H_ + hh)) * S_ + s) * DK + d;
                        if (sel == 0) {
                            g_Qh[idx] = __float2half_rn(val * 0.125f);
                        } else {
                            hsplit(val, hi, lo);
                            g_Kh[idx] = hi; g_Kl[idx] = lo;
                        }
                    }
                }
            }
}

// ---------------------------------------------------------------------------
// Flash attention, fp16 2-term: S = Q·Kh + Q·Kl (Q single), O += P·Vh + P·Vl
// (P single fp16). q128/kv64, 2-stage cp.async K/V.
// smem: sQ 128xAS + 2 stages x {Kh,Kl,Vh,Vl} 64xAS = 92160 B.
// ---------------------------------------------------------------------------
#define AS 72
#define QAR (128 * AS)
#define KVAR (64 * AS)
#define KVARB (KVAR * 2)
#define KVSGB (4 * KVARB)
__global__ __launch_bounds__(256, 2) void attn_f16()
{
    extern __shared__ __align__(16) __half smh[];
    __half* sQ  = smh;
    __half* sKV = smh + QAR;

    const int t = threadIdx.x, lane = t & 31, wid = t >> 5;
    const int g = lane >> 2, l4 = lane & 3;
    const int qt = blockIdx.x, hh = blockIdx.y, b = blockIdx.z;
    const int bhid = b * H_ + hh;
    const int q0 = qt * 128;
    const int wq = wid * 16;

    // stage Q once
    {
        const int row = t >> 1, cs = (t & 1) * 32;
        const __half* gq = g_Qh + ((size_t)bhid * S_ + q0 + row) * DK + cs;
        const uint32_t dq = smem_u32(&sQ[row * AS + cs]);
#pragma unroll
        for (int u = 0; u < 4; u++)
            cpa16(dq + 16 * u, gq + 8 * u);
    }

    const int kr = t >> 2, kcs = (t & 3) * 16;
    const __half* gkh = g_Kh + ((size_t)bhid * S_ + kr) * DK + kcs;
    const __half* gkl = g_Kl + ((size_t)bhid * S_ + kr) * DK + kcs;
    const __half* gvh = g_Vh + ((size_t)bhid * DK + kr) * S_ + kcs;
    const __half* gvl = g_Vl + ((size_t)bhid * DK + kr) * S_ + kcs;
    const uint32_t kvBase = smem_u32(&sKV[kr * AS + kcs]);

#pragma unroll
    for (int u = 0; u < 2; u++) {
        cpa16(kvBase + 0 * KVARB + 16 * u, gkh + 8 * u);
        cpa16(kvBase + 1 * KVARB + 16 * u, gkl + 8 * u);
        cpa16(kvBase + 2 * KVARB + 16 * u, gvh + 8 * u);
        cpa16(kvBase + 3 * KVARB + 16 * u, gvl + 8 * u);
    }
    cp_commit();

    const int fr = lane & 15, fc = (lane >> 4) * 8;
    const uint32_t aQ = smem_u32(&sQ[(wq + fr) * AS + fc]);
    uint32_t aK[4], aV[4];
#pragma unroll
    for (int hq = 0; hq < 4; hq++) {
        const uint32_t rowb = smem_u32(&sKV[(hq * 16 + fr) * AS + fc]);
        aK[hq] = rowb;                 // +KVARB for Kl
        aV[hq] = rowb + 2 * KVARB;     // +KVARB for Vl
    }

    float o[8][4];
#pragma unroll
    for (int na = 0; na < 8; na++)
#pragma unroll
        for (int v = 0; v < 4; v++) o[na][v] = 0.0f;
    float m0r = -1e30f, m1r = -1e30f, l0r = 0.0f, l1r = 0.0f;

    const int NT = S_ / 64;
    for (int jt = 0; jt < NT; jt++) {
        cp_wait<0>();
        __syncthreads();

        if (jt + 1 < NT) {
            const uint32_t sb = kvBase + ((jt + 1) & 1) * KVSGB;
            const int kro = (jt + 1) * 64 * DK;
            const int vco = (jt + 1) * 64;
#pragma unroll
            for (int u = 0; u < 2; u++) {
                cpa16(sb + 0 * KVARB + 16 * u, gkh + kro + 8 * u);
                cpa16(sb + 1 * KVARB + 16 * u, gkl + kro + 8 * u);
                cpa16(sb + 2 * KVARB + 16 * u, gvh + vco + 8 * u);
                cpa16(sb + 3 * KVARB + 16 * u, gvl + vco + 8 * u);
            }
        }
        cp_commit();

        const uint32_t sb = (jt & 1) * KVSGB;

        // ---- S = Q @ K^T (2-term) ----
        float sc[8][4];
#pragma unroll
        for (int na = 0; na < 8; na++)
#pragma unroll
            for (int v = 0; v < 4; v++) sc[na][v] = 0.0f;

#pragma unroll
        for (int kk = 0; kk < 4; kk++) {
            uint32_t q[4];
            ldsm4(q, aQ + kk * 32);
#pragma unroll
            for (int half = 0; half < 2; half++) {
                uint32_t t0[4], t1[4], u0[4], u1[4];
                ldsm4(t0, aK[half * 2 + 0] + sb + kk * 32);
                ldsm4(t1, aK[half * 2 + 1] + sb + kk * 32);
                ldsm4(u0, aK[half * 2 + 0] + sb + KVARB + kk * 32);
                ldsm4(u1, aK[half * 2 + 1] + sb + KVARB + kk * 32);
                const uint32_t bh[4][2] = {{t0[0], t0[2]}, {t0[1], t0[3]},
                                           {t1[0], t1[2]}, {t1[1], t1[3]}};
                const uint32_t bl[4][2] = {{u0[0], u0[2]}, {u0[1], u0[3]},
                                           {u1[0], u1[2]}, {u1[1], u1[3]}};
#pragma unroll
                for (int na = 0; na < 4; na++) {
                    mma_f16(sc[half * 4 + na], q, bh[na][0], bh[na][1]);
                    mma_f16(sc[half * 4 + na], q, bl[na][0], bl[na][1]);
                }
            }
        }

        // ---- warp-local online softmax ----
        float rm0 = -1e30f, rm1 = -1e30f;
#pragma unroll
        for (int na = 0; na < 8; na++) {
            rm0 = fmaxf(rm0, fmaxf(sc[na][0], sc[na][1]));
            rm1 = fmaxf(rm1, fmaxf(sc[na][2], sc[na][3]));
        }
#pragma unroll
        for (int off = 1; off < 4; off <<= 1) {
            rm0 = fmaxf(rm0, __shfl_xor_sync(0xffffffffu, rm0, off));
            rm1 = fmaxf(rm1, __shfl_xor_sync(0xffffffffu, rm1, off));
        }
        const float mn0 = fmaxf(m0r, rm0), mn1 = fmaxf(m1r, rm1);
        const float cor0 = __expf(m0r - mn0), cor1 = __expf(m1r - mn1);
        float rs0 = 0.0f, rs1 = 0.0f;
#pragma unroll
        for (int na = 0; na < 8; na++) {
            sc[na][0] = __expf(sc[na][0] - mn0);
            sc[na][1] = __expf(sc[na][1] - mn0);
            sc[na][2] = __expf(sc[na][2] - mn1);
            sc[na][3] = __expf(sc[na][3] - mn1);
            rs0 += sc[na][0] + sc[na][1];
            rs1 += sc[na][2] + sc[na][3];
        }
#pragma unroll
        for (int off = 1; off < 4; off <<= 1) {
            rs0 += __shfl_xor_sync(0xffffffffu, rs0, off);
            rs1 += __shfl_xor_sync(0xffffffffu, rs1, off);
        }
        l0r = l0r * cor0 + rs0;
        l1r = l1r * cor1 + rs1;
        m0r = mn0; m1r = mn1;
#pragma unroll
        for (int na = 0; na < 8; na++) {
            o[na][0] *= cor0; o[na][1] *= cor0;
            o[na][2] *= cor1; o[na][3] *= cor1;
        }

        // ---- O += P @ V (2-term, P single fp16 from registers) ----
#pragma unroll
        for (int kk = 0; kk < 4; kk++) {
            uint32_t pa[4];
            pa[0] = pkh(__float2half_rn(sc[2 * kk][0]), __float2half_rn(sc[2 * kk][1]));
            pa[1] = pkh(__float2half_rn(sc[2 * kk][2]), __float2half_rn(sc[2 * kk][3]));
            pa[2] = pkh(__float2half_rn(sc[2 * kk + 1][0]), __float2half_rn(sc[2 * kk + 1][1]));
            pa[3] = pkh(__float2half_rn(sc[2 * kk + 1][2]), __float2half_rn(sc[2 * kk + 1][3]));
#pragma unroll
            for (int half = 0; half < 2; half++) {
                uint32_t t0[4], t1[4], u0[4], u1[4];
                ldsm4(t0, aV[half * 2 + 0] + sb + kk * 32);
                ldsm4(t1, aV[half * 2 + 1] + sb + kk * 32);
                ldsm4(u0, aV[half * 2 + 0] + sb + KVARB + kk * 32);
                ldsm4(u1, aV[half * 2 + 1] + sb + KVARB + kk * 32);
                const uint32_t bh[4][2] = {{t0[0], t0[2]}, {t0[1], t0[3]},
                                           {t1[0], t1[2]}, {t1[1], t1[3]}};
                const uint32_t bl[4][2] = {{u0[0], u0[2]}, {u0[1], u0[3]},
                                           {u1[0], u1[2]}, {u1[1], u1[3]}};
#pragma unroll
                for (int na = 0; na < 4; na++) {
                    mma_f16(o[half * 4 + na], pa, bh[na][0], bh[na][1]);
                    mma_f16(o[half * 4 + na], pa, bl[na][0], bl[na][1]);
                }
            }
        }
    }

    // epilogue: fp16, head-major [m][hh*64 + d]
    {
        const float inv0 = 1.0f / l0r, inv1 = 1.0f / l1r;
        const int s0 = q0 + wq + g, s1 = s0 + 8;
        const int bm0 = b * S_ + s0, bm1 = b * S_ + s1;
#pragma unroll
        for (int na = 0; na < 8; na++) {
            const int dd = na * 8 + 2 * l4;
            const size_t i0 = (size_t)bm0 * D_ + hh * 64 + dd;
            const size_t i1 = (size_t)bm1 * D_ + hh * 64 + dd;
            *(uint32_t*)&g_Aih[i0] = pkh(__float2half_rn(o[na][0] * inv0),
                                         __float2half_rn(o[na][1] * inv0));
            *(uint32_t*)&g_Aih[i1] = pkh(__float2half_rn(o[na][2] * inv1),
                                         __float2half_rn(o[na][3] * inv1));
        }
    }
}

// ---------------------------------------------------------------------------
extern "C" void kernel_launch(void* const* d_in, const int* in_sizes, int n_in,
                              void* d_out, int out_size)
{
    const float* xs    = (const float*)d_in[0];
    const float* w_qkv = (const float*)d_in[2];
    const float* w_out = (const float*)d_in[3];
    float* out = (float*)d_out;

    __half *Xh, *Wqh, *Woh, *Wol, *Aih;
    cudaGetSymbolAddress((void**)&Xh,  g_Xh);
    cudaGetSymbolAddress((void**)&Wqh, g_Wqh);
    cudaGetSymbolAddress((void**)&Woh, g_Woh);
    cudaGetSymbolAddress((void**)&Wol, g_Wol);
    cudaGetSymbolAddress((void**)&Aih, g_Aih);

    const int smem_qkv = GST * 2 * GARRB;   // 73728
    const int smem_op  = GST * 3 * GARRB;   // 110592
    cudaFuncSetAttribute((const void*)gemm_f16<1, 1>,
                         cudaFuncAttributeMaxDynamicSharedMemorySize, smem_qkv);
    cudaFuncSetAttribute((const void*)gemm_f16<0, 2>,
                         cudaFuncAttributeMaxDynamicSharedMemorySize, smem_op);

    // 0) pre-split inputs
    split_h<<<(M_ * D_) / 1024, 256>>>(xs, Xh, M_ * D_);
    split_h<<<(3 * D_ * D_) / 1024, 256>>>(w_qkv, Wqh, 3 * D_ * D_);
    split_wout_hl<<<(D_ * D_) / 1024, 256>>>(w_out, Woh, Wol);

    // 1) QKV projection (fp16 single-term)
    {
        dim3 grid(3 * D_ / 128, M_ / 128);
        gemm_f16<1, 1><<<grid, 256, smem_qkv>>>(Xh, Wqh, nullptr, nullptr,
                                                M_, 3 * D_, D_);
    }

    // 2) flash attention (fp16 2-term)
    {
        const int smem = QAR * 2 + 2 * KVSGB;  // 92160
        cudaFuncSetAttribute(attn_f16,
                             cudaFuncAttributeMaxDynamicSharedMemorySize, smem);
        dim3 grid(S_ / 128, H_, B_);
        attn_f16<<<grid, 256, smem>>>();
    }

    // 3) out-projection (fp16 2-term, permuted weights)
    {
        dim3 grid(D_ / 128, M_ / 128);
        gemm_f16<0, 2><<<grid, 256, smem_op>>>(Aih, Woh, Wol, out,
                                               M_, D_, D_);
    }
}

// round 10
// speedup vs baseline: 1.5827x; 1.0535x over previous
#include <cuda_runtime.h>
#include <cuda_fp16.h>
#include <cstdint>

#define H_ 16
#define D_ 1024
#define DK 64
#define B_ 2
#define S_ 2048
#define M_ (B_ * S_)   // 4096

// ---------------- device scratch ----------------
__device__ __half g_Xh [M_ * D_];                         // xs fp16
__device__ __half g_Wqh[3 * D_ * D_];                     // w_qkv fp16
__device__ __half g_Woh[D_ * D_];                         // w_out fp16 PERMUTED [e][h*64+d]
__device__ __half g_Aih[M_ * D_];                         // atn head-major fp16
__device__ __half g_Qh[B_*H_*S_*DK];                      // Q fp16, pre-scaled 1/8
__device__ __half g_Kh[B_*H_*S_*DK],  g_Kl[B_*H_*S_*DK];  // K fp16 hi/lo
__device__ __half g_Vh[B_*H_*DK*S_],  g_Vl[B_*H_*DK*S_];  // V^T [b,h,d,s] hi/lo

// ---------------- helpers ----------------
__device__ __forceinline__ void hsplit(float x, __half& h, __half& l) {
    h = __float2half_rn(x);
    l = __float2half_rn(x - __half2float(h));
}
__device__ __forceinline__ uint32_t pkh(__half a, __half b) {
    return (uint32_t)__half_as_ushort(a) |
           ((uint32_t)__half_as_ushort(b) << 16);
}
__device__ __forceinline__ uint32_t smem_u32(const void* p) {
    return (uint32_t)__cvta_generic_to_shared(p);
}
__device__ __forceinline__ void ldsm4(uint32_t r[4], uint32_t addr) {
    asm volatile("ldmatrix.sync.aligned.m8n8.x4.shared.b16 {%0,%1,%2,%3}, [%4];"
                 : "=r"(r[0]), "=r"(r[1]), "=r"(r[2]), "=r"(r[3]) : "r"(addr));
}
__device__ __forceinline__ void mma_f16(float c[4], const uint32_t a[4],
                                        uint32_t b0, uint32_t b1) {
    asm volatile(
        "mma.sync.aligned.m16n8k16.row.col.f32.f16.f16.f32 "
        "{%0,%1,%2,%3}, {%4,%5,%6,%7}, {%8,%9}, {%0,%1,%2,%3};\n"
        : "+f"(c[0]), "+f"(c[1]), "+f"(c[2]), "+f"(c[3])
        : "r"(a[0]), "r"(a[1]), "r"(a[2]), "r"(a[3]), "r"(b0), "r"(b1));
}
__device__ __forceinline__ void cpa16(uint32_t saddr, const void* g) {
    asm volatile("cp.async.cg.shared.global [%0], [%1], 16;"
                 :: "r"(saddr), "l"(g));
}
__device__ __forceinline__ void cp_commit() {
    asm volatile("cp.async.commit_group;");
}
template <int N>
__device__ __forceinline__ void cp_wait() {
    asm volatile("cp.async.wait_group %0;" :: "n"(N));
}

// ---------------- split passes ----------------
__global__ __launch_bounds__(256) void split_h(
    const float* __restrict__ x, __half* __restrict__ h, int n)
{
    const int i = (blockIdx.x * 256 + threadIdx.x) * 4;
    if (i >= n) return;
    float4 v = *(const float4*)(x + i);
    *(uint32_t*)(h + i)     = pkh(__float2half_rn(v.x), __float2half_rn(v.y));
    *(uint32_t*)(h + i + 2) = pkh(__float2half_rn(v.z), __float2half_rn(v.w));
}
// w_out fp16 with head-major column permutation: out[e][h*64+d] = w[e][d*16+h]
__global__ __launch_bounds__(256) void split_wout_h(
    const float* __restrict__ w, __half* __restrict__ oh)
{
    const int j4 = (blockIdx.x * 256 + threadIdx.x) * 4;
    const int e  = j4 >> 10;
    const int jj = j4 & 1023;
    const int h  = jj >> 6, d = jj & 63;
    const float* src = w + (size_t)e * D_ + h;
    *(uint32_t*)(oh + j4)     = pkh(__float2half_rn(src[(d + 0) * 16]),
                                    __float2half_rn(src[(d + 1) * 16]));
    *(uint32_t*)(oh + j4 + 2) = pkh(__float2half_rn(src[(d + 2) * 16]),
                                    __float2half_rn(src[(d + 3) * 16]));
}

// ---------------------------------------------------------------------------
// fp16 GEMM: C = A @ W^T (both fp16 single-term).
// Block 128x128, BK=64 (4 panels/iter), 2-stage cp.async double buffer.
// 8 warps (4Mx2N), warp tile 32x64. 128 MMAs per warp per barrier.
// smem: 2 stages x 2 arrays x 4 panels x 6144B = 98304 B.
// ---------------------------------------------------------------------------
#define GS 24
#define GPNLB (128 * GS * 2)      // panel bytes: 6144
#define GARRB (4 * GPNLB)         // per-array per-stage: 24576
#define GSGB (2 * GARRB)          // per-stage: 49152
template <int MODE>
__global__ __launch_bounds__(256, 2) void gemm_f16(
    const __half* __restrict__ Ah, const __half* __restrict__ Bh,
    float* __restrict__ C, int M, int N, int K)
{
    extern __shared__ __align__(16) __half sm[];

    const int t = threadIdx.x, lane = t & 31, wid = t >> 5;
    const int g = lane >> 2, l4 = lane & 3;
    const int warpM = wid >> 1, warpN = wid & 1;
    const int m0 = blockIdx.y * 128, n0 = blockIdx.x * 128;

    float c[2][8][4];
#pragma unroll
    for (int i = 0; i < 2; i++)
#pragma unroll
        for (int j = 0; j < 8; j++)
#pragma unroll
            for (int v = 0; v < 4; v++) c[i][j][v] = 0.0f;

    const int srow = t >> 1, sseg = (t & 1) * 8;
    const __half* pAh = Ah + (size_t)(m0 + srow) * K + sseg;
    const __half* pBh = Bh + (size_t)(n0 + srow) * K + sseg;
    const uint32_t stBase = smem_u32(&sm[srow * GS + sseg]);

    const int fr = lane & 15, fc = (lane >> 4) * 8;
    uint32_t aA[2];
#pragma unroll
    for (int ma = 0; ma < 2; ma++)
        aA[ma] = smem_u32(&sm[(warpM * 32 + ma * 16 + fr) * GS + fc]);
    uint32_t aB[4];
#pragma unroll
    for (int hq = 0; hq < 4; hq++)
        aB[hq] = smem_u32(&sm[(warpN * 64 + hq * 16 + fr) * GS + fc]) + GARRB;

    auto load_stage = [&](int c4, int s) {
        const uint32_t sb = stBase + s * GSGB;
#pragma unroll
        for (int p = 0; p < 4; p++) {
            const int k0 = c4 * 64 + p * 16;
            cpa16(sb + 0 * GARRB + p * GPNLB, pAh + k0);
            cpa16(sb + 1 * GARRB + p * GPNLB, pBh + k0);
        }
        cp_commit();
    };

    const int KT4 = K / 64;   // 16
    load_stage(0, 0);

    for (int kt = 0; kt < KT4; kt++) {
        const int st = kt & 1;
        cp_wait<0>();
        __syncthreads();

        if (kt + 1 < KT4) load_stage(kt + 1, st ^ 1);

        const uint32_t stOff = st * GSGB;
#pragma unroll
        for (int p = 0; p < 4; p++) {
            const uint32_t sb = stOff + p * GPNLB;
            uint32_t fA[2][4];
            ldsm4(fA[0], aA[0] + sb);
            ldsm4(fA[1], aA[1] + sb);
            uint32_t bh[4][4];
#pragma unroll
            for (int hq = 0; hq < 4; hq++)
                ldsm4(bh[hq], aB[hq] + sb);
#pragma unroll
            for (int na = 0; na < 8; na++) {
                const int hq = na >> 1, q = na & 1;
#pragma unroll
                for (int ma = 0; ma < 2; ma++)
                    mma_f16(c[ma][na], fA[ma], bh[hq][q], bh[hq][q + 2]);
            }
        }
    }

    // epilogue
#pragma unroll
    for (int ma = 0; ma < 2; ma++)
#pragma unroll
        for (int na = 0; na < 8; na++)
#pragma unroll
            for (int v = 0; v < 4; v++) {
                const int m = m0 + warpM * 32 + ma * 16 + g + ((v >= 2) ? 8 : 0);
                const int n = n0 + warpN * 64 + na * 8 + 2 * l4 + (v & 1);
                const float val = c[ma][na][v];
                if (MODE == 0) {
                    C[(size_t)m * N + n] = val;
                } else {
                    const int s = m & (S_ - 1), b = m >> 11;
                    const int sel = n >> 10, e = n & 1023;
                    const int hh = e & 15, d = e >> 4;
                    __half hi, lo;
                    if (sel == 2) {
                        hsplit(val, hi, lo);
                        const size_t vi = (((size_t)(b * H_ + hh)) * DK + d) * S_ + s;
                        g_Vh[vi] = hi; g_Vl[vi] = lo;
                    } else {
                        const size_t idx = (((size_t)(b * H_ + hh)) * S_ + s) * DK + d;
                        if (sel == 0) {
                            g_Qh[idx] = __float2half_rn(val * 0.125f);
                        } else {
                            hsplit(val, hi, lo);
                            g_Kh[idx] = hi; g_Kl[idx] = lo;
                        }
                    }
                }
            }
}

// ---------------------------------------------------------------------------
// Flash attention, fp16 2-term (unchanged from R9): S = Q·Kh + Q·Kl,
// O += P·Vh + P·Vl. q128/kv64, 2-stage cp.async K/V.
// ---------------------------------------------------------------------------
#define AS 72
#define QAR (128 * AS)
#define KVAR (64 * AS)
#define KVARB (KVAR * 2)
#define KVSGB (4 * KVARB)
__global__ __launch_bounds__(256, 2) void attn_f16()
{
    extern __shared__ __align__(16) __half smh[];
    __half* sQ  = smh;
    __half* sKV = smh + QAR;

    const int t = threadIdx.x, lane = t & 31, wid = t >> 5;
    const int g = lane >> 2, l4 = lane & 3;
    const int qt = blockIdx.x, hh = blockIdx.y, b = blockIdx.z;
    const int bhid = b * H_ + hh;
    const int q0 = qt * 128;
    const int wq = wid * 16;

    {
        const int row = t >> 1, cs = (t & 1) * 32;
        const __half* gq = g_Qh + ((size_t)bhid * S_ + q0 + row) * DK + cs;
        const uint32_t dq = smem_u32(&sQ[row * AS + cs]);
#pragma unroll
        for (int u = 0; u < 4; u++)
            cpa16(dq + 16 * u, gq + 8 * u);
    }

    const int kr = t >> 2, kcs = (t & 3) * 16;
    const __half* gkh = g_Kh + ((size_t)bhid * S_ + kr) * DK + kcs;
    const __half* gkl = g_Kl + ((size_t)bhid * S_ + kr) * DK + kcs;
    const __half* gvh = g_Vh + ((size_t)bhid * DK + kr) * S_ + kcs;
    const __half* gvl = g_Vl + ((size_t)bhid * DK + kr) * S_ + kcs;
    const uint32_t kvBase = smem_u32(&sKV[kr * AS + kcs]);

#pragma unroll
    for (int u = 0; u < 2; u++) {
        cpa16(kvBase + 0 * KVARB + 16 * u, gkh + 8 * u);
        cpa16(kvBase + 1 * KVARB + 16 * u, gkl + 8 * u);
        cpa16(kvBase + 2 * KVARB + 16 * u, gvh + 8 * u);
        cpa16(kvBase + 3 * KVARB + 16 * u, gvl + 8 * u);
    }
    cp_commit();

    const int fr = lane & 15, fc = (lane >> 4) * 8;
    const uint32_t aQ = smem_u32(&sQ[(wq + fr) * AS + fc]);
    uint32_t aK[4], aV[4];
#pragma unroll
    for (int hq = 0; hq < 4; hq++) {
        const uint32_t rowb = smem_u32(&sKV[(hq * 16 + fr) * AS + fc]);
        aK[hq] = rowb;
        aV[hq] = rowb + 2 * KVARB;
    }

    float o[8][4];
#pragma unroll
    for (int na = 0; na < 8; na++)
#pragma unroll
        for (int v = 0; v < 4; v++) o[na][v] = 0.0f;
    float m0r = -1e30f, m1r = -1e30f, l0r = 0.0f, l1r = 0.0f;

    const int NT = S_ / 64;
    for (int jt = 0; jt < NT; jt++) {
        cp_wait<0>();
        __syncthreads();

        if (jt + 1 < NT) {
            const uint32_t sb = kvBase + ((jt + 1) & 1) * KVSGB;
            const int kro = (jt + 1) * 64 * DK;
            const int vco = (jt + 1) * 64;
#pragma unroll
            for (int u = 0; u < 2; u++) {
                cpa16(sb + 0 * KVARB + 16 * u, gkh + kro + 8 * u);
                cpa16(sb + 1 * KVARB + 16 * u, gkl + kro + 8 * u);
                cpa16(sb + 2 * KVARB + 16 * u, gvh + vco + 8 * u);
                cpa16(sb + 3 * KVARB + 16 * u, gvl + vco + 8 * u);
            }
        }
        cp_commit();

        const uint32_t sb = (jt & 1) * KVSGB;

        float sc[8][4];
#pragma unroll
        for (int na = 0; na < 8; na++)
#pragma unroll
            for (int v = 0; v < 4; v++) sc[na][v] = 0.0f;

#pragma unroll
        for (int kk = 0; kk < 4; kk++) {
            uint32_t q[4];
            ldsm4(q, aQ + kk * 32);
#pragma unroll
            for (int half = 0; half < 2; half++) {
                uint32_t t0[4], t1[4], u0[4], u1[4];
                ldsm4(t0, aK[half * 2 + 0] + sb + kk * 32);
                ldsm4(t1, aK[half * 2 + 1] + sb + kk * 32);
                ldsm4(u0, aK[half * 2 + 0] + sb + KVARB + kk * 32);
                ldsm4(u1, aK[half * 2 + 1] + sb + KVARB + kk * 32);
                const uint32_t bh[4][2] = {{t0[0], t0[2]}, {t0[1], t0[3]},
                                           {t1[0], t1[2]}, {t1[1], t1[3]}};
                const uint32_t bl[4][2] = {{u0[0], u0[2]}, {u0[1], u0[3]},
                                           {u1[0], u1[2]}, {u1[1], u1[3]}};
#pragma unroll
                for (int na = 0; na < 4; na++) {
                    mma_f16(sc[half * 4 + na], q, bh[na][0], bh[na][1]);
                    mma_f16(sc[half * 4 + na], q, bl[na][0], bl[na][1]);
                }
            }
        }

        float rm0 = -1e30f, rm1 = -1e30f;
#pragma unroll
        for (int na = 0; na < 8; na++) {
            rm0 = fmaxf(rm0, fmaxf(sc[na][0], sc[na][1]));
            rm1 = fmaxf(rm1, fmaxf(sc[na][2], sc[na][3]));
        }
#pragma unroll
        for (int off = 1; off < 4; off <<= 1) {
            rm0 = fmaxf(rm0, __shfl_xor_sync(0xffffffffu, rm0, off));
            rm1 = fmaxf(rm1, __shfl_xor_sync(0xffffffffu, rm1, off));
        }
        const float mn0 = fmaxf(m0r, rm0), mn1 = fmaxf(m1r, rm1);
        const float cor0 = __expf(m0r - mn0), cor1 = __expf(m1r - mn1);
        float rs0 = 0.0f, rs1 = 0.0f;
#pragma unroll
        for (int na = 0; na < 8; na++) {
            sc[na][0] = __expf(sc[na][0] - mn0);
            sc[na][1] = __expf(sc[na][1] - mn0);
            sc[na][2] = __expf(sc[na][2] - mn1);
            sc[na][3] = __expf(sc[na][3] - mn1);
            rs0 += sc[na][0] + sc[na][1];
            rs1 += sc[na][2] + sc[na][3];
        }
#pragma unroll
        for (int off = 1; off < 4; off <<= 1) {
            rs0 += __shfl_xor_sync(0xffffffffu, rs0, off);
            rs1 += __shfl_xor_sync(0xffffffffu, rs1, off);
        }
        l0r = l0r * cor0 + rs0;
        l1r = l1r * cor1 + rs1;
        m0r = mn0; m1r = mn1;
#pragma unroll
        for (int na = 0; na < 8; na++) {
            o[na][0] *= cor0; o[na][1] *= cor0;
            o[na][2] *= cor1; o[na][3] *= cor1;
        }

#pragma unroll
        for (int kk = 0; kk < 4; kk++) {
            uint32_t pa[4];
            pa[0] = pkh(__float2half_rn(sc[2 * kk][0]), __float2half_rn(sc[2 * kk][1]));
            pa[1] = pkh(__float2half_rn(sc[2 * kk][2]), __float2half_rn(sc[2 * kk][3]));
            pa[2] = pkh(__float2half_rn(sc[2 * kk + 1][0]), __float2half_rn(sc[2 * kk + 1][1]));
            pa[3] = pkh(__float2half_rn(sc[2 * kk + 1][2]), __float2half_rn(sc[2 * kk + 1][3]));
#pragma unroll
            for (int half = 0; half < 2; half++) {
                uint32_t t0[4], t1[4], u0[4], u1[4];
                ldsm4(t0, aV[half * 2 + 0] + sb + kk * 32);
                ldsm4(t1, aV[half * 2 + 1] + sb + kk * 32);
                ldsm4(u0, aV[half * 2 + 0] + sb + KVARB + kk * 32);
                ldsm4(u1, aV[half * 2 + 1] + sb + KVARB + kk * 32);
                const uint32_t bh[4][2] = {{t0[0], t0[2]}, {t0[1], t0[3]},
                                           {t1[0], t1[2]}, {t1[1], t1[3]}};
                const uint32_t bl[4][2] = {{u0[0], u0[2]}, {u0[1], u0[3]},
                                           {u1[0], u1[2]}, {u1[1], u1[3]}};
#pragma unroll
                for (int na = 0; na < 4; na++) {
                    mma_f16(o[half * 4 + na], pa, bh[na][0], bh[na][1]);
                    mma_f16(o[half * 4 + na], pa, bl[na][0], bl[na][1]);
                }
            }
        }
    }

    {
        const float inv0 = 1.0f / l0r, inv1 = 1.0f / l1r;
        const int s0 = q0 + wq + g, s1 = s0 + 8;
        const int bm0 = b * S_ + s0, bm1 = b * S_ + s1;
#pragma unroll
        for (int na = 0; na < 8; na++) {
            const int dd = na * 8 + 2 * l4;
            const size_t i0 = (size_t)bm0 * D_ + hh * 64 + dd;
            const size_t i1 = (size_t)bm1 * D_ + hh * 64 + dd;
            *(uint32_t*)&g_Aih[i0] = pkh(__float2half_rn(o[na][0] * inv0),
                                         __float2half_rn(o[na][1] * inv0));
            *(uint32_t*)&g_Aih[i1] = pkh(__float2half_rn(o[na][2] * inv1),
                                         __float2half_rn(o[na][3] * inv1));
        }
    }
}

// ---------------------------------------------------------------------------
extern "C" void kernel_launch(void* const* d_in, const int* in_sizes, int n_in,
                              void* d_out, int out_size)
{
    const float* xs    = (const float*)d_in[0];
    const float* w_qkv = (const float*)d_in[2];
    const float* w_out = (const float*)d_in[3];
    float* out = (float*)d_out;

    __half *Xh, *Wqh, *Woh, *Aih;
    cudaGetSymbolAddress((void**)&Xh,  g_Xh);
    cudaGetSymbolAddress((void**)&Wqh, g_Wqh);
    cudaGetSymbolAddress((void**)&Woh, g_Woh);
    cudaGetSymbolAddress((void**)&Aih, g_Aih);

    const int gemm_smem = 2 * GSGB;          // 98304
    cudaFuncSetAttribute((const void*)gemm_f16<0>,
                         cudaFuncAttributeMaxDynamicSharedMemorySize, gemm_smem);
    cudaFuncSetAttribute((const void*)gemm_f16<1>,
                         cudaFuncAttributeMaxDynamicSharedMemorySize, gemm_smem);

    // 0) pre-split inputs (fp16)
    split_h<<<(M_ * D_) / 1024, 256>>>(xs, Xh, M_ * D_);
    split_h<<<(3 * D_ * D_) / 1024, 256>>>(w_qkv, Wqh, 3 * D_ * D_);
    split_wout_h<<<(D_ * D_) / 1024, 256>>>(w_out, Woh);

    // 1) QKV projection
    {
        dim3 grid(3 * D_ / 128, M_ / 128);
        gemm_f16<1><<<grid, 256, gemm_smem>>>(Xh, Wqh, nullptr, M_, 3 * D_, D_);
    }

    // 2) flash attention (fp16 2-term)
    {
        const int smem = QAR * 2 + 2 * KVSGB;  // 92160
        cudaFuncSetAttribute(attn_f16,
                             cudaFuncAttributeMaxDynamicSharedMemorySize, smem);
        dim3 grid(S_ / 128, H_, B_);
        attn_f16<<<grid, 256, smem>>>();
    }

    // 3) out-projection (permuted fp16 weights)
    {
        dim3 grid(D_ / 128, M_ / 128);
        gemm_f16<0><<<grid, 256, gemm_smem>>>(Aih, Woh, out, M_, D_, D_);
    }
}

// round 11
// speedup vs baseline: 1.9964x; 1.2614x over previous
#include <cuda_runtime.h>
#include <cuda_fp16.h>
#include <cstdint>

#define H_ 16
#define D_ 1024
#define DK 64
#define B_ 2
#define S_ 2048
#define M_ (B_ * S_)   // 4096

// ---------------- device scratch ----------------
__device__ __half g_Xh [M_ * D_];                         // xs fp16
__device__ __half g_Wqh[3 * D_ * D_];                     // w_qkv fp16
__device__ __half g_Woh[D_ * D_];                         // w_out fp16 PERMUTED [e][h*64+d]
__device__ __half g_Aih[M_ * D_];                         // atn head-major fp16
__device__ __half g_Qh[B_*H_*S_*DK];                      // Q fp16, pre-scaled 1/8
__device__ __half g_Kh[B_*H_*S_*DK],  g_Kl[B_*H_*S_*DK];  // K fp16 hi/lo
__device__ __half g_Vh[B_*H_*DK*S_],  g_Vl[B_*H_*DK*S_];  // V^T [b,h,d,s] hi/lo

// ---------------- helpers ----------------
__device__ __forceinline__ void hsplit(float x, __half& h, __half& l) {
    h = __float2half_rn(x);
    l = __float2half_rn(x - __half2float(h));
}
__device__ __forceinline__ uint32_t pkh(__half a, __half b) {
    return (uint32_t)__half_as_ushort(a) |
           ((uint32_t)__half_as_ushort(b) << 16);
}
__device__ __forceinline__ uint32_t smem_u32(const void* p) {
    return (uint32_t)__cvta_generic_to_shared(p);
}
__device__ __forceinline__ void ldsm4(uint32_t r[4], uint32_t addr) {
    asm volatile("ldmatrix.sync.aligned.m8n8.x4.shared.b16 {%0,%1,%2,%3}, [%4];"
                 : "=r"(r[0]), "=r"(r[1]), "=r"(r[2]), "=r"(r[3]) : "r"(addr));
}
__device__ __forceinline__ void mma_f16(float c[4], const uint32_t a[4],
                                        uint32_t b0, uint32_t b1) {
    asm volatile(
        "mma.sync.aligned.m16n8k16.row.col.f32.f16.f16.f32 "
        "{%0,%1,%2,%3}, {%4,%5,%6,%7}, {%8,%9}, {%0,%1,%2,%3};\n"
        : "+f"(c[0]), "+f"(c[1]), "+f"(c[2]), "+f"(c[3])
        : "r"(a[0]), "r"(a[1]), "r"(a[2]), "r"(a[3]), "r"(b0), "r"(b1));
}
__device__ __forceinline__ void cpa16(uint32_t saddr, const void* g) {
    asm volatile("cp.async.cg.shared.global [%0], [%1], 16;"
                 :: "r"(saddr), "l"(g));
}
__device__ __forceinline__ void cp_commit() {
    asm volatile("cp.async.commit_group;");
}
template <int N>
__device__ __forceinline__ void cp_wait() {
    asm volatile("cp.async.wait_group %0;" :: "n"(N));
}

// ---------------- split passes ----------------
__global__ __launch_bounds__(256) void split_h(
    const float* __restrict__ x, __half* __restrict__ h, int n)
{
    const int i = (blockIdx.x * 256 + threadIdx.x) * 4;
    if (i >= n) return;
    float4 v = *(const float4*)(x + i);
    *(uint32_t*)(h + i)     = pkh(__float2half_rn(v.x), __float2half_rn(v.y));
    *(uint32_t*)(h + i + 2) = pkh(__float2half_rn(v.z), __float2half_rn(v.w));
}
// w_out fp16 with head-major column permutation: out[e][h*64+d] = w[e][d*16+h]
__global__ __launch_bounds__(256) void split_wout_h(
    const float* __restrict__ w, __half* __restrict__ oh)
{
    const int j4 = (blockIdx.x * 256 + threadIdx.x) * 4;
    const int e  = j4 >> 10;
    const int jj = j4 & 1023;
    const int h  = jj >> 6, d = jj & 63;
    const float* src = w + (size_t)e * D_ + h;
    *(uint32_t*)(oh + j4)     = pkh(__float2half_rn(src[(d + 0) * 16]),
                                    __float2half_rn(src[(d + 1) * 16]));
    *(uint32_t*)(oh + j4 + 2) = pkh(__float2half_rn(src[(d + 2) * 16]),
                                    __float2half_rn(src[(d + 3) * 16]));
}

// ---------------------------------------------------------------------------
// fp16 GEMM: C = A @ W^T (both fp16 single-term).
// Block 128x128, BK=64 (4 panels/iter), 2-stage cp.async double buffer.
// 8 warps (4Mx2N), warp tile 32x64.
// MODE 0: coalesced float2 stores. MODE 1: smem-staged coalesced QKV scatter.
// ---------------------------------------------------------------------------
#define GS 24
#define GPNLB (128 * GS * 2)      // panel bytes: 6144
#define GARRB (4 * GPNLB)         // per-array per-stage: 24576
#define GSGB (2 * GARRB)          // per-stage: 49152
#define SCP 132                   // epilogue smem stride (floats)
template <int MODE>
__global__ __launch_bounds__(256, 2) void gemm_f16(
    const __half* __restrict__ Ah, const __half* __restrict__ Bh,
    float* __restrict__ C, int M, int N, int K)
{
    extern __shared__ __align__(16) __half sm[];

    const int t = threadIdx.x, lane = t & 31, wid = t >> 5;
    const int g = lane >> 2, l4 = lane & 3;
    const int warpM = wid >> 1, warpN = wid & 1;
    const int m0 = blockIdx.y * 128, n0 = blockIdx.x * 128;

    float c[2][8][4];
#pragma unroll
    for (int i = 0; i < 2; i++)
#pragma unroll
        for (int j = 0; j < 8; j++)
#pragma unroll
            for (int v = 0; v < 4; v++) c[i][j][v] = 0.0f;

    const int srow = t >> 1, sseg = (t & 1) * 8;
    const __half* pAh = Ah + (size_t)(m0 + srow) * K + sseg;
    const __half* pBh = Bh + (size_t)(n0 + srow) * K + sseg;
    const uint32_t stBase = smem_u32(&sm[srow * GS + sseg]);

    const int fr = lane & 15, fc = (lane >> 4) * 8;
    uint32_t aA[2];
#pragma unroll
    for (int ma = 0; ma < 2; ma++)
        aA[ma] = smem_u32(&sm[(warpM * 32 + ma * 16 + fr) * GS + fc]);
    uint32_t aB[4];
#pragma unroll
    for (int hq = 0; hq < 4; hq++)
        aB[hq] = smem_u32(&sm[(warpN * 64 + hq * 16 + fr) * GS + fc]) + GARRB;

    auto load_stage = [&](int c4, int s) {
        const uint32_t sb = stBase + s * GSGB;
#pragma unroll
        for (int p = 0; p < 4; p++) {
            const int k0 = c4 * 64 + p * 16;
            cpa16(sb + 0 * GARRB + p * GPNLB, pAh + k0);
            cpa16(sb + 1 * GARRB + p * GPNLB, pBh + k0);
        }
        cp_commit();
    };

    const int KT4 = K / 64;   // 16
    load_stage(0, 0);

    for (int kt = 0; kt < KT4; kt++) {
        const int st = kt & 1;
        cp_wait<0>();
        __syncthreads();

        if (kt + 1 < KT4) load_stage(kt + 1, st ^ 1);

        const uint32_t stOff = st * GSGB;
#pragma unroll
        for (int p = 0; p < 4; p++) {
            const uint32_t sb = stOff + p * GPNLB;
            uint32_t fA[2][4];
            ldsm4(fA[0], aA[0] + sb);
            ldsm4(fA[1], aA[1] + sb);
            uint32_t bh[4][4];
#pragma unroll
            for (int hq = 0; hq < 4; hq++)
                ldsm4(bh[hq], aB[hq] + sb);
#pragma unroll
            for (int na = 0; na < 8; na++) {
                const int hq = na >> 1, q = na & 1;
#pragma unroll
                for (int ma = 0; ma < 2; ma++)
                    mma_f16(c[ma][na], fA[ma], bh[hq][q], bh[hq][q + 2]);
            }
        }
    }

    if (MODE == 0) {
        // coalesced float2 stores (v0,v1 and v2,v3 are adjacent columns)
#pragma unroll
        for (int ma = 0; ma < 2; ma++)
#pragma unroll
            for (int na = 0; na < 8; na++) {
                const int m1 = m0 + warpM * 32 + ma * 16 + g;
                const int n  = n0 + warpN * 64 + na * 8 + 2 * l4;
                *(float2*)&C[(size_t)m1 * N + n] =
                    make_float2(c[ma][na][0], c[ma][na][1]);
                *(float2*)&C[(size_t)(m1 + 8) * N + n] =
                    make_float2(c[ma][na][2], c[ma][na][3]);
            }
    } else {
        // smem-staged coalesced QKV scatter
        __syncthreads();              // pipeline smem reads all done
        float* sC = (float*)sm;       // [128 n_local][SCP m_local]
#pragma unroll
        for (int ma = 0; ma < 2; ma++)
#pragma unroll
            for (int na = 0; na < 8; na++)
#pragma unroll
                for (int v = 0; v < 4; v++) {
                    const int ml = warpM * 32 + ma * 16 + g + ((v >= 2) ? 8 : 0);
                    const int nl = warpN * 64 + na * 8 + 2 * l4 + (v & 1);
                    sC[nl * SCP + ml] = c[ma][na][v];
                }
        __syncthreads();

        const int sel = n0 >> 10;            // 0=Q, 1=K, 2=V
        const int bI  = m0 >> 11;
        const int s0g = m0 & (S_ - 1);
        const int d0  = (n0 & 1023) >> 4;    // tile's first d (multiple of 8)

        if (sel == 2) {
            // V: 128 (h,dd) runs of 128 s-contiguous halves; 2 threads per run
            const int run = t >> 1, half = t & 1;
            const int hhh = run & 15, dd = run >> 4;
            const float* src = &sC[(dd * 16 + hhh) * SCP + half * 64];
            __half hb[64], lb[64];
#pragma unroll
            for (int j = 0; j < 64; j++) hsplit(src[j], hb[j], lb[j]);
            const size_t base = (((size_t)(bI * H_ + hhh)) * DK + d0 + dd) * S_
                              + s0g + half * 64;
#pragma unroll
            for (int j = 0; j < 8; j++) {
                *(uint4*)&g_Vh[base + j * 8] = *(uint4*)&hb[j * 8];
                *(uint4*)&g_Vl[base + j * 8] = *(uint4*)&lb[j * 8];
            }
        } else {
            // Q/K: 2048 (h,s) runs of 8 d-contiguous halves; 8 runs per thread
#pragma unroll
            for (int i = 0; i < 8; i++) {
                const int run = t + i * 256;
                const int hhh = run >> 7, s = run & 127;
                __half hb[8], lb[8];
#pragma unroll
                for (int dd = 0; dd < 8; dd++) {
                    const float vL = sC[(dd * 16 + hhh) * SCP + s];
                    if (sel == 0) hb[dd] = __float2half_rn(vL * 0.125f);
                    else          hsplit(vL, hb[dd], lb[dd]);
                }
                const size_t idx = (((size_t)(bI * H_ + hhh)) * S_ + s0g + s) * DK + d0;
                if (sel == 0) {
                    *(uint4*)&g_Qh[idx] = *(uint4*)&hb[0];
                } else {
                    *(uint4*)&g_Kh[idx] = *(uint4*)&hb[0];
                    *(uint4*)&g_Kl[idx] = *(uint4*)&lb[0];
                }
            }
        }
    }
}

// ---------------------------------------------------------------------------
// Flash attention, fp16 2-term (unchanged): S = Q·Kh + Q·Kl, O += P·Vh + P·Vl.
// q128/kv64, 2-stage cp.async K/V.
// ---------------------------------------------------------------------------
#define AS 72
#define QAR (128 * AS)
#define KVAR (64 * AS)
#define KVARB (KVAR * 2)
#define KVSGB (4 * KVARB)
__global__ __launch_bounds__(256, 2) void attn_f16()
{
    extern __shared__ __align__(16) __half smh[];
    __half* sQ  = smh;
    __half* sKV = smh + QAR;

    const int t = threadIdx.x, lane = t & 31, wid = t >> 5;
    const int g = lane >> 2, l4 = lane & 3;
    const int qt = blockIdx.x, hh = blockIdx.y, b = blockIdx.z;
    const int bhid = b * H_ + hh;
    const int q0 = qt * 128;
    const int wq = wid * 16;

    {
        const int row = t >> 1, cs = (t & 1) * 32;
        const __half* gq = g_Qh + ((size_t)bhid * S_ + q0 + row) * DK + cs;
        const uint32_t dq = smem_u32(&sQ[row * AS + cs]);
#pragma unroll
        for (int u = 0; u < 4; u++)
            cpa16(dq + 16 * u, gq + 8 * u);
    }

    const int kr = t >> 2, kcs = (t & 3) * 16;
    const __half* gkh = g_Kh + ((size_t)bhid * S_ + kr) * DK + kcs;
    const __half* gkl = g_Kl + ((size_t)bhid * S_ + kr) * DK + kcs;
    const __half* gvh = g_Vh + ((size_t)bhid * DK + kr) * S_ + kcs;
    const __half* gvl = g_Vl + ((size_t)bhid * DK + kr) * S_ + kcs;
    const uint32_t kvBase = smem_u32(&sKV[kr * AS + kcs]);

#pragma unroll
    for (int u = 0; u < 2; u++) {
        cpa16(kvBase + 0 * KVARB + 16 * u, gkh + 8 * u);
        cpa16(kvBase + 1 * KVARB + 16 * u, gkl + 8 * u);
        cpa16(kvBase + 2 * KVARB + 16 * u, gvh + 8 * u);
        cpa16(kvBase + 3 * KVARB + 16 * u, gvl + 8 * u);
    }
    cp_commit();

    const int fr = lane & 15, fc = (lane >> 4) * 8;
    const uint32_t aQ = smem_u32(&sQ[(wq + fr) * AS + fc]);
    uint32_t aK[4], aV[4];
#pragma unroll
    for (int hq = 0; hq < 4; hq++) {
        const uint32_t rowb = smem_u32(&sKV[(hq * 16 + fr) * AS + fc]);
        aK[hq] = rowb;
        aV[hq] = rowb + 2 * KVARB;
    }

    float o[8][4];
#pragma unroll
    for (int na = 0; na < 8; na++)
#pragma unroll
        for (int v = 0; v < 4; v++) o[na][v] = 0.0f;
    float m0r = -1e30f, m1r = -1e30f, l0r = 0.0f, l1r = 0.0f;

    const int NT = S_ / 64;
    for (int jt = 0; jt < NT; jt++) {
        cp_wait<0>();
        __syncthreads();

        if (jt + 1 < NT) {
            const uint32_t sb = kvBase + ((jt + 1) & 1) * KVSGB;
            const int kro = (jt + 1) * 64 * DK;
            const int vco = (jt + 1) * 64;
#pragma unroll
            for (int u = 0; u < 2; u++) {
                cpa16(sb + 0 * KVARB + 16 * u, gkh + kro + 8 * u);
                cpa16(sb + 1 * KVARB + 16 * u, gkl + kro + 8 * u);
                cpa16(sb + 2 * KVARB + 16 * u, gvh + vco + 8 * u);
                cpa16(sb + 3 * KVARB + 16 * u, gvl + vco + 8 * u);
            }
        }
        cp_commit();

        const uint32_t sb = (jt & 1) * KVSGB;

        float sc[8][4];
#pragma unroll
        for (int na = 0; na < 8; na++)
#pragma unroll
            for (int v = 0; v < 4; v++) sc[na][v] = 0.0f;

#pragma unroll
        for (int kk = 0; kk < 4; kk++) {
            uint32_t q[4];
            ldsm4(q, aQ + kk * 32);
#pragma unroll
            for (int half = 0; half < 2; half++) {
                uint32_t t0[4], t1[4], u0[4], u1[4];
                ldsm4(t0, aK[half * 2 + 0] + sb + kk * 32);
                ldsm4(t1, aK[half * 2 + 1] + sb + kk * 32);
                ldsm4(u0, aK[half * 2 + 0] + sb + KVARB + kk * 32);
                ldsm4(u1, aK[half * 2 + 1] + sb + KVARB + kk * 32);
                const uint32_t bh[4][2] = {{t0[0], t0[2]}, {t0[1], t0[3]},
                                           {t1[0], t1[2]}, {t1[1], t1[3]}};
                const uint32_t bl[4][2] = {{u0[0], u0[2]}, {u0[1], u0[3]},
                                           {u1[0], u1[2]}, {u1[1], u1[3]}};
#pragma unroll
                for (int na = 0; na < 4; na++) {
                    mma_f16(sc[half * 4 + na], q, bh[na][0], bh[na][1]);
                    mma_f16(sc[half * 4 + na], q, bl[na][0], bl[na][1]);
                }
            }
        }

        float rm0 = -1e30f, rm1 = -1e30f;
#pragma unroll
        for (int na = 0; na < 8; na++) {
            rm0 = fmaxf(rm0, fmaxf(sc[na][0], sc[na][1]));
            rm1 = fmaxf(rm1, fmaxf(sc[na][2], sc[na][3]));
        }
#pragma unroll
        for (int off = 1; off < 4; off <<= 1) {
            rm0 = fmaxf(rm0, __shfl_xor_sync(0xffffffffu, rm0, off));
            rm1 = fmaxf(rm1, __shfl_xor_sync(0xffffffffu, rm1, off));
        }
        const float mn0 = fmaxf(m0r, rm0), mn1 = fmaxf(m1r, rm1);
        const float cor0 = __expf(m0r - mn0), cor1 = __expf(m1r - mn1);
        float rs0 = 0.0f, rs1 = 0.0f;
#pragma unroll
        for (int na = 0; na < 8; na++) {
            sc[na][0] = __expf(sc[na][0] - mn0);
            sc[na][1] = __expf(sc[na][1] - mn0);
            sc[na][2] = __expf(sc[na][2] - mn1);
            sc[na][3] = __expf(sc[na][3] - mn1);
            rs0 += sc[na][0] + sc[na][1];
            rs1 += sc[na][2] + sc[na][3];
        }
#pragma unroll
        for (int off = 1; off < 4; off <<= 1) {
            rs0 += __shfl_xor_sync(0xffffffffu, rs0, off);
            rs1 += __shfl_xor_sync(0xffffffffu, rs1, off);
        }
        l0r = l0r * cor0 + rs0;
        l1r = l1r * cor1 + rs1;
        m0r = mn0; m1r = mn1;
#pragma unroll
        for (int na = 0; na < 8; na++) {
            o[na][0] *= cor0; o[na][1] *= cor0;
            o[na][2] *= cor1; o[na][3] *= cor1;
        }

#pragma unroll
        for (int kk = 0; kk < 4; kk++) {
            uint32_t pa[4];
            pa[0] = pkh(__float2half_rn(sc[2 * kk][0]), __float2half_rn(sc[2 * kk][1]));
            pa[1] = pkh(__float2half_rn(sc[2 * kk][2]), __float2half_rn(sc[2 * kk][3]));
            pa[2] = pkh(__float2half_rn(sc[2 * kk + 1][0]), __float2half_rn(sc[2 * kk + 1][1]));
            pa[3] = pkh(__float2half_rn(sc[2 * kk + 1][2]), __float2half_rn(sc[2 * kk + 1][3]));
#pragma unroll
            for (int half = 0; half < 2; half++) {
                uint32_t t0[4], t1[4], u0[4], u1[4];
                ldsm4(t0, aV[half * 2 + 0] + sb + kk * 32);
                ldsm4(t1, aV[half * 2 + 1] + sb + kk * 32);
                ldsm4(u0, aV[half * 2 + 0] + sb + KVARB + kk * 32);
                ldsm4(u1, aV[half * 2 + 1] + sb + KVARB + kk * 32);
                const uint32_t bh[4][2] = {{t0[0], t0[2]}, {t0[1], t0[3]},
                                           {t1[0], t1[2]}, {t1[1], t1[3]}};
                const uint32_t bl[4][2] = {{u0[0], u0[2]}, {u0[1], u0[3]},
                                           {u1[0], u1[2]}, {u1[1], u1[3]}};
#pragma unroll
                for (int na = 0; na < 4; na++) {
                    mma_f16(o[half * 4 + na], pa, bh[na][0], bh[na][1]);
                    mma_f16(o[half * 4 + na], pa, bl[na][0], bl[na][1]);
                }
            }
        }
    }

    {
        const float inv0 = 1.0f / l0r, inv1 = 1.0f / l1r;
        const int s0 = q0 + wq + g, s1 = s0 + 8;
        const int bm0 = b * S_ + s0, bm1 = b * S_ + s1;
#pragma unroll
        for (int na = 0; na < 8; na++) {
            const int dd = na * 8 + 2 * l4;
            const size_t i0 = (size_t)bm0 * D_ + hh * 64 + dd;
            const size_t i1 = (size_t)bm1 * D_ + hh * 64 + dd;
            *(uint32_t*)&g_Aih[i0] = pkh(__float2half_rn(o[na][0] * inv0),
                                         __float2half_rn(o[na][1] * inv0));
            *(uint32_t*)&g_Aih[i1] = pkh(__float2half_rn(o[na][2] * inv1),
                                         __float2half_rn(o[na][3] * inv1));
        }
    }
}

// ---------------------------------------------------------------------------
extern "C" void kernel_launch(void* const* d_in, const int* in_sizes, int n_in,
                              void* d_out, int out_size)
{
    const float* xs    = (const float*)d_in[0];
    const float* w_qkv = (const float*)d_in[2];
    const float* w_out = (const float*)d_in[3];
    float* out = (float*)d_out;

    __half *Xh, *Wqh, *Woh, *Aih;
    cudaGetSymbolAddress((void**)&Xh,  g_Xh);
    cudaGetSymbolAddress((void**)&Wqh, g_Wqh);
    cudaGetSymbolAddress((void**)&Woh, g_Woh);
    cudaGetSymbolAddress((void**)&Aih, g_Aih);

    const int gemm_smem = 2 * GSGB;          // 98304
    cudaFuncSetAttribute((const void*)gemm_f16<0>,
                         cudaFuncAttributeMaxDynamicSharedMemorySize, gemm_smem);
    cudaFuncSetAttribute((const void*)gemm_f16<1>,
                         cudaFuncAttributeMaxDynamicSharedMemorySize, gemm_smem);

    // 0) pre-split inputs (fp16)
    split_h<<<(M_ * D_) / 1024, 256>>>(xs, Xh, M_ * D_);
    split_h<<<(3 * D_ * D_) / 1024, 256>>>(w_qkv, Wqh, 3 * D_ * D_);
    split_wout_h<<<(D_ * D_) / 1024, 256>>>(w_out, Woh);

    // 1) QKV projection
    {
        dim3 grid(3 * D_ / 128, M_ / 128);
        gemm_f16<1><<<grid, 256, gemm_smem>>>(Xh, Wqh, nullptr, M_, 3 * D_, D_);
    }

    // 2) flash attention (fp16 2-term)
    {
        const int smem = QAR * 2 + 2 * KVSGB;  // 92160
        cudaFuncSetAttribute(attn_f16,
                             cudaFuncAttributeMaxDynamicSharedMemorySize, smem);
        dim3 grid(S_ / 128, H_, B_);
        attn_f16<<<grid, 256, smem>>>();
    }

    // 3) out-projection (permuted fp16 weights)
    {
        dim3 grid(D_ / 128, M_ / 128);
        gemm_f16<0><<<grid, 256, gemm_smem>>>(Aih, Woh, out, M_, D_, D_);
    }
}

// round 12
// speedup vs baseline: 2.3914x; 1.1978x over previous
#include <cuda_runtime.h>
#include <cuda_fp16.h>
#include <cstdint>

#define H_ 16
#define D_ 1024
#define DK 64
#define B_ 2
#define S_ 2048
#define M_ (B_ * S_)   // 4096

// ---------------- device scratch ----------------
__device__ __half g_Xh [M_ * D_];                         // xs fp16
__device__ __half g_Wqh[3 * D_ * D_];                     // w_qkv fp16
__device__ __half g_Woh[D_ * D_];                         // w_out fp16 PERMUTED [e][h*64+d]
__device__ __half g_Aih[M_ * D_];                         // atn head-major fp16
__device__ __half g_Qh[B_*H_*S_*DK];                      // Q fp16, pre-scaled 1/8
__device__ __half g_Kh[B_*H_*S_*DK],  g_Kl[B_*H_*S_*DK];  // K fp16 hi/lo
__device__ __half g_Vh[B_*H_*DK*S_];                      // V^T [b,h,d,s] fp16

// ---------------- helpers ----------------
__device__ __forceinline__ void hsplit(float x, __half& h, __half& l) {
    h = __float2half_rn(x);
    l = __float2half_rn(x - __half2float(h));
}
__device__ __forceinline__ uint32_t pkh(__half a, __half b) {
    return (uint32_t)__half_as_ushort(a) |
           ((uint32_t)__half_as_ushort(b) << 16);
}
__device__ __forceinline__ uint32_t smem_u32(const void* p) {
    return (uint32_t)__cvta_generic_to_shared(p);
}
__device__ __forceinline__ void ldsm4(uint32_t r[4], uint32_t addr) {
    asm volatile("ldmatrix.sync.aligned.m8n8.x4.shared.b16 {%0,%1,%2,%3}, [%4];"
                 : "=r"(r[0]), "=r"(r[1]), "=r"(r[2]), "=r"(r[3]) : "r"(addr));
}
__device__ __forceinline__ void mma_f16(float c[4], const uint32_t a[4],
                                        uint32_t b0, uint32_t b1) {
    asm volatile(
        "mma.sync.aligned.m16n8k16.row.col.f32.f16.f16.f32 "
        "{%0,%1,%2,%3}, {%4,%5,%6,%7}, {%8,%9}, {%0,%1,%2,%3};\n"
        : "+f"(c[0]), "+f"(c[1]), "+f"(c[2]), "+f"(c[3])
        : "r"(a[0]), "r"(a[1]), "r"(a[2]), "r"(a[3]), "r"(b0), "r"(b1));
}
__device__ __forceinline__ void cpa16(uint32_t saddr, const void* g) {
    asm volatile("cp.async.cg.shared.global [%0], [%1], 16;"
                 :: "r"(saddr), "l"(g));
}
__device__ __forceinline__ void cp_commit() {
    asm volatile("cp.async.commit_group;");
}
template <int N>
__device__ __forceinline__ void cp_wait() {
    asm volatile("cp.async.wait_group %0;" :: "n"(N));
}

// ---------------- split passes ----------------
__global__ __launch_bounds__(256) void split_h(
    const float* __restrict__ x, __half* __restrict__ h, int n)
{
    const int i = (blockIdx.x * 256 + threadIdx.x) * 4;
    if (i >= n) return;
    float4 v = *(const float4*)(x + i);
    *(uint32_t*)(h + i)     = pkh(__float2half_rn(v.x), __float2half_rn(v.y));
    *(uint32_t*)(h + i + 2) = pkh(__float2half_rn(v.z), __float2half_rn(v.w));
}
// w_out fp16 with head-major column permutation: out[e][h*64+d] = w[e][d*16+h]
__global__ __launch_bounds__(256) void split_wout_h(
    const float* __restrict__ w, __half* __restrict__ oh)
{
    const int j4 = (blockIdx.x * 256 + threadIdx.x) * 4;
    const int e  = j4 >> 10;
    const int jj = j4 & 1023;
    const int h  = jj >> 6, d = jj & 63;
    const float* src = w + (size_t)e * D_ + h;
    *(uint32_t*)(oh + j4)     = pkh(__float2half_rn(src[(d + 0) * 16]),
                                    __float2half_rn(src[(d + 1) * 16]));
    *(uint32_t*)(oh + j4 + 2) = pkh(__float2half_rn(src[(d + 2) * 16]),
                                    __float2half_rn(src[(d + 3) * 16]));
}

// ---------------------------------------------------------------------------
// fp16 GEMM: C = A @ W^T (both fp16 single-term).
// Block 128x128, BK=64 (4 panels/iter), 2-stage cp.async double buffer.
// MODE 0: coalesced float2 stores. MODE 1: smem-staged coalesced QKV scatter.
// ---------------------------------------------------------------------------
#define GS 24
#define GPNLB (128 * GS * 2)      // panel bytes: 6144
#define GARRB (4 * GPNLB)         // per-array per-stage: 24576
#define GSGB (2 * GARRB)          // per-stage: 49152
#define SCP 132                   // epilogue smem stride (floats)
template <int MODE>
__global__ __launch_bounds__(256, 2) void gemm_f16(
    const __half* __restrict__ Ah, const __half* __restrict__ Bh,
    float* __restrict__ C, int M, int N, int K)
{
    extern __shared__ __align__(16) __half sm[];

    const int t = threadIdx.x, lane = t & 31, wid = t >> 5;
    const int g = lane >> 2, l4 = lane & 3;
    const int warpM = wid >> 1, warpN = wid & 1;
    const int m0 = blockIdx.y * 128, n0 = blockIdx.x * 128;

    float c[2][8][4];
#pragma unroll
    for (int i = 0; i < 2; i++)
#pragma unroll
        for (int j = 0; j < 8; j++)
#pragma unroll
            for (int v = 0; v < 4; v++) c[i][j][v] = 0.0f;

    const int srow = t >> 1, sseg = (t & 1) * 8;
    const __half* pAh = Ah + (size_t)(m0 + srow) * K + sseg;
    const __half* pBh = Bh + (size_t)(n0 + srow) * K + sseg;
    const uint32_t stBase = smem_u32(&sm[srow * GS + sseg]);

    const int fr = lane & 15, fc = (lane >> 4) * 8;
    uint32_t aA[2];
#pragma unroll
    for (int ma = 0; ma < 2; ma++)
        aA[ma] = smem_u32(&sm[(warpM * 32 + ma * 16 + fr) * GS + fc]);
    uint32_t aB[4];
#pragma unroll
    for (int hq = 0; hq < 4; hq++)
        aB[hq] = smem_u32(&sm[(warpN * 64 + hq * 16 + fr) * GS + fc]) + GARRB;

    auto load_stage = [&](int c4, int s) {
        const uint32_t sb = stBase + s * GSGB;
#pragma unroll
        for (int p = 0; p < 4; p++) {
            const int k0 = c4 * 64 + p * 16;
            cpa16(sb + 0 * GARRB + p * GPNLB, pAh + k0);
            cpa16(sb + 1 * GARRB + p * GPNLB, pBh + k0);
        }
        cp_commit();
    };

    const int KT4 = K / 64;   // 16
    load_stage(0, 0);

    for (int kt = 0; kt < KT4; kt++) {
        const int st = kt & 1;
        cp_wait<0>();
        __syncthreads();

        if (kt + 1 < KT4) load_stage(kt + 1, st ^ 1);

        const uint32_t stOff = st * GSGB;
#pragma unroll
        for (int p = 0; p < 4; p++) {
            const uint32_t sb = stOff + p * GPNLB;
            uint32_t fA[2][4];
            ldsm4(fA[0], aA[0] + sb);
            ldsm4(fA[1], aA[1] + sb);
            uint32_t bh[4][4];
#pragma unroll
            for (int hq = 0; hq < 4; hq++)
                ldsm4(bh[hq], aB[hq] + sb);
#pragma unroll
            for (int na = 0; na < 8; na++) {
                const int hq = na >> 1, q = na & 1;
#pragma unroll
                for (int ma = 0; ma < 2; ma++)
                    mma_f16(c[ma][na], fA[ma], bh[hq][q], bh[hq][q + 2]);
            }
        }
    }

    if (MODE == 0) {
#pragma unroll
        for (int ma = 0; ma < 2; ma++)
#pragma unroll
            for (int na = 0; na < 8; na++) {
                const int m1 = m0 + warpM * 32 + ma * 16 + g;
                const int n  = n0 + warpN * 64 + na * 8 + 2 * l4;
                *(float2*)&C[(size_t)m1 * N + n] =
                    make_float2(c[ma][na][0], c[ma][na][1]);
                *(float2*)&C[(size_t)(m1 + 8) * N + n] =
                    make_float2(c[ma][na][2], c[ma][na][3]);
            }
    } else {
        // smem-staged coalesced QKV scatter
        __syncthreads();
        float* sC = (float*)sm;       // [128 n_local][SCP m_local]
#pragma unroll
        for (int ma = 0; ma < 2; ma++)
#pragma unroll
            for (int na = 0; na < 8; na++)
#pragma unroll
                for (int v = 0; v < 4; v++) {
                    const int ml = warpM * 32 + ma * 16 + g + ((v >= 2) ? 8 : 0);
                    const int nl = warpN * 64 + na * 8 + 2 * l4 + (v & 1);
                    sC[nl * SCP + ml] = c[ma][na][v];
                }
        __syncthreads();

        const int sel = n0 >> 10;            // 0=Q, 1=K, 2=V
        const int bI  = m0 >> 11;
        const int s0g = m0 & (S_ - 1);
        const int d0  = (n0 & 1023) >> 4;

        if (sel == 2) {
            // V: single fp16, 128 (h,dd) runs of 128 s-contiguous halves
            const int run = t >> 1, half = t & 1;
            const int hhh = run & 15, dd = run >> 4;
            const float* src = &sC[(dd * 16 + hhh) * SCP + half * 64];
            __half hb[64];
#pragma unroll
            for (int j = 0; j < 64; j++) hb[j] = __float2half_rn(src[j]);
            const size_t base = (((size_t)(bI * H_ + hhh)) * DK + d0 + dd) * S_
                              + s0g + half * 64;
#pragma unroll
            for (int j = 0; j < 8; j++)
                *(uint4*)&g_Vh[base + j * 8] = *(uint4*)&hb[j * 8];
        } else {
            // Q/K: 2048 (h,s) runs of 8 d-contiguous halves
#pragma unroll
            for (int i = 0; i < 8; i++) {
                const int run = t + i * 256;
                const int hhh = run >> 7, s = run & 127;
                __half hb[8], lb[8];
#pragma unroll
                for (int dd = 0; dd < 8; dd++) {
                    const float vL = sC[(dd * 16 + hhh) * SCP + s];
                    if (sel == 0) hb[dd] = __float2half_rn(vL * 0.125f);
                    else          hsplit(vL, hb[dd], lb[dd]);
                }
                const size_t idx = (((size_t)(bI * H_ + hhh)) * S_ + s0g + s) * DK + d0;
                if (sel == 0) {
                    *(uint4*)&g_Qh[idx] = *(uint4*)&hb[0];
                } else {
                    *(uint4*)&g_Kh[idx] = *(uint4*)&hb[0];
                    *(uint4*)&g_Kl[idx] = *(uint4*)&lb[0];
                }
            }
        }
    }
}

// ---------------------------------------------------------------------------
// Flash attention: q-tile 256, 512 threads (16 warps x 16 q-rows), kv-tile 64.
// S = Q·Kh + Q·Kl (K 2-term); O += P·Vh (V single). 2-stage cp.async K/V.
// smem: sQ 256xAS + 2 stages x {Kh,Kl,Vh} 64xAS = 92160 B.
// ---------------------------------------------------------------------------
#define AS 72
#define QAR (256 * AS)
#define KVAR (64 * AS)
#define KVARB (KVAR * 2)          // 9216 B per array
#define KVSGB (3 * KVARB)         // 27648 B per stage
__global__ __launch_bounds__(512, 1) void attn_f16()
{
    extern __shared__ __align__(16) __half smh[];
    __half* sQ  = smh;
    __half* sKV = smh + QAR;

    const int t = threadIdx.x, lane = t & 31, wid = t >> 5;
    const int g = lane >> 2, l4 = lane & 3;
    const int qt = blockIdx.x, hh = blockIdx.y, b = blockIdx.z;
    const int bhid = b * H_ + hh;
    const int q0 = qt * 256;
    const int wq = wid * 16;       // wid 0..15

    // stage Q (256 rows): 2 threads/row, 64B each
    {
        const int row = t >> 1, cs = (t & 1) * 32;
        const __half* gq = g_Qh + ((size_t)bhid * S_ + q0 + row) * DK + cs;
        const uint32_t dq = smem_u32(&sQ[row * AS + cs]);
#pragma unroll
        for (int u = 0; u < 4; u++)
            cpa16(dq + 16 * u, gq + 8 * u);
    }

    // K/V staging: 8 threads/row, 16B each (64 rows per array)
    const int kr = t >> 3, kcs = (t & 7) * 8;
    const __half* gkh = g_Kh + ((size_t)bhid * S_ + kr) * DK + kcs;
    const __half* gkl = g_Kl + ((size_t)bhid * S_ + kr) * DK + kcs;
    const __half* gvh = g_Vh + ((size_t)bhid * DK + kr) * S_ + kcs;
    const uint32_t kvBase = smem_u32(&sKV[kr * AS + kcs]);

    cpa16(kvBase + 0 * KVARB, gkh);
    cpa16(kvBase + 1 * KVARB, gkl);
    cpa16(kvBase + 2 * KVARB, gvh);
    cp_commit();

    const int fr = lane & 15, fc = (lane >> 4) * 8;
    const uint32_t aQ = smem_u32(&sQ[(wq + fr) * AS + fc]);
    uint32_t aK[4], aV[4];
#pragma unroll
    for (int hq = 0; hq < 4; hq++) {
        const uint32_t rowb = smem_u32(&sKV[(hq * 16 + fr) * AS + fc]);
        aK[hq] = rowb;                 // +KVARB for Kl
        aV[hq] = rowb + 2 * KVARB;
    }

    float o[8][4];
#pragma unroll
    for (int na = 0; na < 8; na++)
#pragma unroll
        for (int v = 0; v < 4; v++) o[na][v] = 0.0f;
    float m0r = -1e30f, m1r = -1e30f, l0r = 0.0f, l1r = 0.0f;

    const int NT = S_ / 64;
    for (int jt = 0; jt < NT; jt++) {
        cp_wait<0>();
        __syncthreads();

        if (jt + 1 < NT) {
            const uint32_t sb = kvBase + ((jt + 1) & 1) * KVSGB;
            const int kro = (jt + 1) * 64 * DK;
            const int vco = (jt + 1) * 64;
            cpa16(sb + 0 * KVARB, gkh + kro);
            cpa16(sb + 1 * KVARB, gkl + kro);
            cpa16(sb + 2 * KVARB, gvh + vco);
        }
        cp_commit();

        const uint32_t sb = (jt & 1) * KVSGB;

        // ---- S = Q @ K^T (K 2-term) ----
        float sc[8][4];
#pragma unroll
        for (int na = 0; na < 8; na++)
#pragma unroll
            for (int v = 0; v < 4; v++) sc[na][v] = 0.0f;

#pragma unroll
        for (int kk = 0; kk < 4; kk++) {
            uint32_t q[4];
            ldsm4(q, aQ + kk * 32);
#pragma unroll
            for (int half = 0; half < 2; half++) {
                uint32_t t0[4], t1[4], u0[4], u1[4];
                ldsm4(t0, aK[half * 2 + 0] + sb + kk * 32);
                ldsm4(t1, aK[half * 2 + 1] + sb + kk * 32);
                ldsm4(u0, aK[half * 2 + 0] + sb + KVARB + kk * 32);
                ldsm4(u1, aK[half * 2 + 1] + sb + KVARB + kk * 32);
                const uint32_t bh[4][2] = {{t0[0], t0[2]}, {t0[1], t0[3]},
                                           {t1[0], t1[2]}, {t1[1], t1[3]}};
                const uint32_t bl[4][2] = {{u0[0], u0[2]}, {u0[1], u0[3]},
                                           {u1[0], u1[2]}, {u1[1], u1[3]}};
#pragma unroll
                for (int na = 0; na < 4; na++) {
                    mma_f16(sc[half * 4 + na], q, bh[na][0], bh[na][1]);
                    mma_f16(sc[half * 4 + na], q, bl[na][0], bl[na][1]);
                }
            }
        }

        // ---- warp-local online softmax ----
        float rm0 = -1e30f, rm1 = -1e30f;
#pragma unroll
        for (int na = 0; na < 8; na++) {
            rm0 = fmaxf(rm0, fmaxf(sc[na][0], sc[na][1]));
            rm1 = fmaxf(rm1, fmaxf(sc[na][2], sc[na][3]));
        }
#pragma unroll
        for (int off = 1; off < 4; off <<= 1) {
            rm0 = fmaxf(rm0, __shfl_xor_sync(0xffffffffu, rm0, off));
            rm1 = fmaxf(rm1, __shfl_xor_sync(0xffffffffu, rm1, off));
        }
        const float mn0 = fmaxf(m0r, rm0), mn1 = fmaxf(m1r, rm1);
        const float cor0 = __expf(m0r - mn0), cor1 = __expf(m1r - mn1);
        float rs0 = 0.0f, rs1 = 0.0f;
#pragma unroll
        for (int na = 0; na < 8; na++) {
            sc[na][0] = __expf(sc[na][0] - mn0);
            sc[na][1] = __expf(sc[na][1] - mn0);
            sc[na][2] = __expf(sc[na][2] - mn1);
            sc[na][3] = __expf(sc[na][3] - mn1);
            rs0 += sc[na][0] + sc[na][1];
            rs1 += sc[na][2] + sc[na][3];
        }
#pragma unroll
        for (int off = 1; off < 4; off <<= 1) {
            rs0 += __shfl_xor_sync(0xffffffffu, rs0, off);
            rs1 += __shfl_xor_sync(0xffffffffu, rs1, off);
        }
        l0r = l0r * cor0 + rs0;
        l1r = l1r * cor1 + rs1;
        m0r = mn0; m1r = mn1;
#pragma unroll
        for (int na = 0; na < 8; na++) {
            o[na][0] *= cor0; o[na][1] *= cor0;
            o[na][2] *= cor1; o[na][3] *= cor1;
        }

        // ---- O += P @ V (V single, P single fp16 from registers) ----
#pragma unroll
        for (int kk = 0; kk < 4; kk++) {
            uint32_t pa[4];
            pa[0] = pkh(__float2half_rn(sc[2 * kk][0]), __float2half_rn(sc[2 * kk][1]));
            pa[1] = pkh(__float2half_rn(sc[2 * kk][2]), __float2half_rn(sc[2 * kk][3]));
            pa[2] = pkh(__float2half_rn(sc[2 * kk + 1][0]), __float2half_rn(sc[2 * kk + 1][1]));
            pa[3] = pkh(__float2half_rn(sc[2 * kk + 1][2]), __float2half_rn(sc[2 * kk + 1][3]));
#pragma unroll
            for (int half = 0; half < 2; half++) {
                uint32_t t0[4], t1[4];
                ldsm4(t0, aV[half * 2 + 0] + sb + kk * 32);
                ldsm4(t1, aV[half * 2 + 1] + sb + kk * 32);
                const uint32_t bh[4][2] = {{t0[0], t0[2]}, {t0[1], t0[3]},
                                           {t1[0], t1[2]}, {t1[1], t1[3]}};
#pragma unroll
                for (int na = 0; na < 4; na++)
                    mma_f16(o[half * 4 + na], pa, bh[na][0], bh[na][1]);
            }
        }
    }

    // epilogue: fp16, head-major [m][hh*64 + d]
    {
        const float inv0 = 1.0f / l0r, inv1 = 1.0f / l1r;
        const int s0 = q0 + wq + g, s1 = s0 + 8;
        const int bm0 = b * S_ + s0, bm1 = b * S_ + s1;
#pragma unroll
        for (int na = 0; na < 8; na++) {
            const int dd = na * 8 + 2 * l4;
            const size_t i0 = (size_t)bm0 * D_ + hh * 64 + dd;
            const size_t i1 = (size_t)bm1 * D_ + hh * 64 + dd;
            *(uint32_t*)&g_Aih[i0] = pkh(__float2half_rn(o[na][0] * inv0),
                                         __float2half_rn(o[na][1] * inv0));
            *(uint32_t*)&g_Aih[i1] = pkh(__float2half_rn(o[na][2] * inv1),
                                         __float2half_rn(o[na][3] * inv1));
        }
    }
}

// ---------------------------------------------------------------------------
extern "C" void kernel_launch(void* const* d_in, const int* in_sizes, int n_in,
                              void* d_out, int out_size)
{
    const float* xs    = (const float*)d_in[0];
    const float* w_qkv = (const float*)d_in[2];
    const float* w_out = (const float*)d_in[3];
    float* out = (float*)d_out;

    __half *Xh, *Wqh, *Woh, *Aih;
    cudaGetSymbolAddress((void**)&Xh,  g_Xh);
    cudaGetSymbolAddress((void**)&Wqh, g_Wqh);
    cudaGetSymbolAddress((void**)&Woh, g_Woh);
    cudaGetSymbolAddress((void**)&Aih, g_Aih);

    const int gemm_smem = 2 * GSGB;          // 98304
    cudaFuncSetAttribute((const void*)gemm_f16<0>,
                         cudaFuncAttributeMaxDynamicSharedMemorySize, gemm_smem);
    cudaFuncSetAttribute((const void*)gemm_f16<1>,
                         cudaFuncAttributeMaxDynamicSharedMemorySize, gemm_smem);

    // 0) pre-split inputs (fp16)
    split_h<<<(M_ * D_) / 1024, 256>>>(xs, Xh, M_ * D_);
    split_h<<<(3 * D_ * D_) / 1024, 256>>>(w_qkv, Wqh, 3 * D_ * D_);
    split_wout_h<<<(D_ * D_) / 1024, 256>>>(w_out, Woh);

    // 1) QKV projection
    {
        dim3 grid(3 * D_ / 128, M_ / 128);
        gemm_f16<1><<<grid, 256, gemm_smem>>>(Xh, Wqh, nullptr, M_, 3 * D_, D_);
    }

    // 2) flash attention (q-tile 256, 512 threads)
    {
        const int smem = QAR * 2 + 2 * KVSGB;  // 92160
        cudaFuncSetAttribute(attn_f16,
                             cudaFuncAttributeMaxDynamicSharedMemorySize, smem);
        dim3 grid(S_ / 256, H_, B_);  // (8, 16, 2)
        attn_f16<<<grid, 512, smem>>>();
    }

    // 3) out-projection (permuted fp16 weights)
    {
        dim3 grid(D_ / 128, M_ / 128);
        gemm_f16<0><<<grid, 256, gemm_smem>>>(Aih, Woh, out, M_, D_, D_);
    }
}